// round 12
// baseline (speedup 1.0000x reference)
#include <cuda_runtime.h>
#include <cuda_fp16.h>
#include <math.h>
#include <stdint.h>

// Problem constants
#define Bb 4
#define Hh 8
#define BHn 32
#define NN 2048
#define Dd 512
#define DHd 64
#define MF 256
#define CK 128
#define NC 16

// Scratch
__device__ __align__(16) __half g_qp[(size_t)BHn * NN * MF];  // exp'd q feats (half)
__device__ float g_kp[(size_t)BHn * NN * MF];                 // RAW dd - diag (fp32)
__device__ __align__(16) __half g_kph[(size_t)BHn * NN * MF]; // exp'd k feats (half)
__device__ __align__(16) __half g_S[(size_t)BHn * NC * MF * DHd]; // S (half)
__device__ float g_z [BHn * NC * MF];
__device__ float g_kmax[BHn];

__device__ __forceinline__ float tf32r(float x) {
    uint32_t u = __float_as_uint(x);
    u = (u + 0x1000u) & 0xFFFFE000u;
    return __uint_as_float(u);
}
__device__ __forceinline__ uint32_t tf32u(float x) {
    return (__float_as_uint(x) + 0x1000u) & 0xFFFFE000u;
}
__device__ __forceinline__ float4 tf32v4(float4 v) {
    v.x = tf32r(v.x); v.y = tf32r(v.y); v.z = tf32r(v.z); v.w = tf32r(v.w);
    return v;
}
__device__ __forceinline__ float kfeat(float v, float m) {
    return 0.0625f * (__expf(v - m) + 1e-4f);
}
__device__ __forceinline__ float4 kfeat4(float4 v, float m) {
    v.x = kfeat(v.x, m); v.y = kfeat(v.y, m);
    v.z = kfeat(v.z, m); v.w = kfeat(v.w, m);
    return v;
}

// Warp-level tf32 MMA (portable ISA; tensor pipe)
__device__ __forceinline__ void mma16n8k8(float c[4], const uint32_t a[4],
                                          const uint32_t b[2]) {
    asm volatile(
        "mma.sync.aligned.m16n8k8.row.col.f32.tf32.tf32.f32 "
        "{%0,%1,%2,%3}, {%4,%5,%6,%7}, {%8,%9}, {%0,%1,%2,%3};"
        : "+f"(c[0]), "+f"(c[1]), "+f"(c[2]), "+f"(c[3])
        : "r"(a[0]), "r"(a[1]), "r"(a[2]), "r"(a[3]), "r"(b[0]), "r"(b[1]));
}

// ---------------------------------------------------------------------------
// Feature-map kernel (split-tf32 tensor core; double-buffered proj staging)
// Q output: exp'd half. K output: raw fp32 (dd - diag) + global max.
// ---------------------------------------------------------------------------
template <bool IS_Q>
__global__ void __launch_bounds__(256) feat_kernel(const float* __restrict__ xin,
                                                   const float* __restrict__ proj) {
    __shared__ uint4 ps[2][1024];
    __shared__ float mx[64][2];
    __shared__ float bred[8];

    const int t = threadIdx.x, wid = t >> 5, lane = t & 31;
    const int g = lane >> 2, tq = lane & 3;
    const int wm = wid >> 1, wn = wid & 1;
    const int bh = blockIdx.y, b = bh >> 3, h = bh & 7;
    const int n0 = blockIdx.x * 64;
    const int r0 = n0 + wm * 16;

    if (IS_Q && blockIdx.x == 0 && t == 0) g_kmax[bh] = -1e30f;

    uint4 ah[8], al[8];
    float ss0 = 0.f, ss1 = 0.f;
    const float* xb = xin + ((size_t)b * NN + r0) * Dd + h * DHd;
#pragma unroll
    for (int ks = 0; ks < 8; ks++) {
        float x0 = xb[(size_t)g * Dd + ks * 8 + tq];
        float x1 = xb[(size_t)(g + 8) * Dd + ks * 8 + tq];
        float x2 = xb[(size_t)g * Dd + ks * 8 + tq + 4];
        float x3 = xb[(size_t)(g + 8) * Dd + ks * 8 + tq + 4];
        ss0 += x0 * x0 + x2 * x2;
        ss1 += x1 * x1 + x3 * x3;
        uint32_t h0 = __float_as_uint(x0) & 0xFFFFE000u;
        uint32_t h1 = __float_as_uint(x1) & 0xFFFFE000u;
        uint32_t h2 = __float_as_uint(x2) & 0xFFFFE000u;
        uint32_t h3 = __float_as_uint(x3) & 0xFFFFE000u;
        ah[ks] = make_uint4(h0, h1, h2, h3);
        al[ks] = make_uint4(__float_as_uint(x0 - __uint_as_float(h0)),
                            __float_as_uint(x1 - __uint_as_float(h1)),
                            __float_as_uint(x2 - __uint_as_float(h2)),
                            __float_as_uint(x3 - __uint_as_float(h3)));
    }
    ss0 += __shfl_xor_sync(0xffffffffu, ss0, 1);
    ss0 += __shfl_xor_sync(0xffffffffu, ss0, 2);
    ss1 += __shfl_xor_sync(0xffffffffu, ss1, 1);
    ss1 += __shfl_xor_sync(0xffffffffu, ss1, 2);
    const float diag0 = ss0 * 0.0625f, diag1 = ss1 * 0.0625f;

    float acc[16][4];
#pragma unroll
    for (int i = 0; i < 16; i++)
#pragma unroll
        for (int j = 0; j < 4; j++) acc[i][j] = 0.f;

    // Prologue: stage ks=0 into buffer 0
#pragma unroll
    for (int it = 0; it < 4; it++) {
        int slot = it * 256 + t;
        int nt = slot >> 5, sl = slot & 31;
        int sg = sl >> 2, stq = sl & 3;
        const float* pp = proj + (nt * 8 + sg) * 64 + stq;
        float p0 = pp[0], p1 = pp[4];
        uint32_t h0 = __float_as_uint(p0) & 0xFFFFE000u;
        uint32_t h1 = __float_as_uint(p1) & 0xFFFFE000u;
        ps[0][slot] = make_uint4(h0, h1,
                                 __float_as_uint(p0 - __uint_as_float(h0)),
                                 __float_as_uint(p1 - __uint_as_float(h1)));
    }

    for (int ks = 0; ks < 8; ks++) {
        __syncthreads();
        if (ks < 7) {
            int sks = ks + 1, buf = sks & 1;
#pragma unroll
            for (int it = 0; it < 4; it++) {
                int slot = it * 256 + t;
                int nt = slot >> 5, sl = slot & 31;
                int sg = sl >> 2, stq = sl & 3;
                const float* pp = proj + (nt * 8 + sg) * 64 + sks * 8 + stq;
                float p0 = pp[0], p1 = pp[4];
                uint32_t h0 = __float_as_uint(p0) & 0xFFFFE000u;
                uint32_t h1 = __float_as_uint(p1) & 0xFFFFE000u;
                ps[buf][slot] = make_uint4(h0, h1,
                                           __float_as_uint(p0 - __uint_as_float(h0)),
                                           __float_as_uint(p1 - __uint_as_float(h1)));
            }
        }
        const uint4* pb = ps[ks & 1];
#pragma unroll
        for (int ntl = 0; ntl < 16; ntl++) {
            uint4 pv = pb[(wn * 16 + ntl) * 32 + lane];
            uint32_t bhi[2] = {pv.x, pv.y};
            uint32_t blo[2] = {pv.z, pv.w};
            mma16n8k8(acc[ntl], (const uint32_t*)&ah[ks], bhi);
            mma16n8k8(acc[ntl], (const uint32_t*)&al[ks], bhi);
            mma16n8k8(acc[ntl], (const uint32_t*)&ah[ks], blo);
        }
    }

    const float normalizer = 0.35355339059327373f;
#pragma unroll
    for (int ntl = 0; ntl < 16; ntl++)
#pragma unroll
        for (int j = 0; j < 4; j++) acc[ntl][j] *= normalizer;

    if (IS_Q) {
        float m0 = -1e30f, m1 = -1e30f;
#pragma unroll
        for (int ntl = 0; ntl < 16; ntl++) {
            m0 = fmaxf(m0, fmaxf(acc[ntl][0], acc[ntl][1]));
            m1 = fmaxf(m1, fmaxf(acc[ntl][2], acc[ntl][3]));
        }
        m0 = fmaxf(m0, __shfl_xor_sync(0xffffffffu, m0, 1));
        m0 = fmaxf(m0, __shfl_xor_sync(0xffffffffu, m0, 2));
        m1 = fmaxf(m1, __shfl_xor_sync(0xffffffffu, m1, 1));
        m1 = fmaxf(m1, __shfl_xor_sync(0xffffffffu, m1, 2));
        if (tq == 0) {
            mx[wm * 16 + g][wn] = m0;
            mx[wm * 16 + g + 8][wn] = m1;
        }
        __syncthreads();
        const float M0 = fmaxf(mx[wm * 16 + g][0], mx[wm * 16 + g][1]);
        const float M1 = fmaxf(mx[wm * 16 + g + 8][0], mx[wm * 16 + g + 8][1]);
        __half* o0 = g_qp + ((size_t)bh * NN + r0 + g) * MF + wn * 128;
        __half* o1 = g_qp + ((size_t)bh * NN + r0 + g + 8) * MF + wn * 128;
#pragma unroll
        for (int ntl = 0; ntl < 16; ntl++) {
            float a0 = 0.0625f * (__expf(acc[ntl][0] - diag0 - M0) + 1e-4f);
            float a1 = 0.0625f * (__expf(acc[ntl][1] - diag0 - M0) + 1e-4f);
            float a2 = 0.0625f * (__expf(acc[ntl][2] - diag1 - M1) + 1e-4f);
            float a3 = 0.0625f * (__expf(acc[ntl][3] - diag1 - M1) + 1e-4f);
            *(__half2*)(o0 + ntl * 8 + tq * 2) = __floats2half2_rn(a0, a1);
            *(__half2*)(o1 + ntl * 8 + tq * 2) = __floats2half2_rn(a2, a3);
        }
    } else {
        float km = -1e30f;
        float* o0 = g_kp + ((size_t)bh * NN + r0 + g) * MF + wn * 128;
        float* o1 = g_kp + ((size_t)bh * NN + r0 + g + 8) * MF + wn * 128;
#pragma unroll
        for (int ntl = 0; ntl < 16; ntl++) {
            km = fmaxf(km, fmaxf(fmaxf(acc[ntl][0], acc[ntl][1]),
                                 fmaxf(acc[ntl][2], acc[ntl][3])));
            float2 v0 = make_float2(acc[ntl][0] - diag0, acc[ntl][1] - diag0);
            float2 v1 = make_float2(acc[ntl][2] - diag1, acc[ntl][3] - diag1);
            *(float2*)(o0 + ntl * 8 + tq * 2) = v0;
            *(float2*)(o1 + ntl * 8 + tq * 2) = v1;
        }
#pragma unroll
        for (int off = 16; off; off >>= 1)
            km = fmaxf(km, __shfl_xor_sync(0xffffffffu, km, off));
        if (lane == 0) bred[wid] = km;
        __syncthreads();
        if (t == 0) {
            float m = bred[0];
            for (int w = 1; w < 8; w++) m = fmaxf(m, bred[w]);
            int* addr = (int*)&g_kmax[bh];
            int old = *addr;
            while (__int_as_float(old) < m) {
                int assumed = old;
                old = atomicCAS(addr, assumed, __float_as_int(m));
                if (old == assumed) break;
            }
        }
    }
}

// ---------------------------------------------------------------------------
// Per-chunk local KV state; also exports exp'd half k' for out_kernel.
// S written as half.
// ---------------------------------------------------------------------------
__global__ void __launch_bounds__(256) chunk_kv_kernel(const float* __restrict__ vin) {
    const int t = threadIdx.x, wid = t >> 5, lane = t & 31;
    const int g = lane >> 2, tq = lane & 3;
    const int c = blockIdx.x, bh = blockIdx.y;
    const int b = bh >> 3, h = bh & 7;
    const int n0 = c * CK;
    const float* kb = g_kp + (size_t)(bh * NN + n0) * MF;
    const float* vb = vin + ((size_t)(b * NN + n0)) * Dd + h * DHd;
    const float m = g_kmax[bh];

    // Export k' = kfeat(kraw) as half (coalesced; kb becomes L2-warm)
    {
        __half* kph = g_kph + (size_t)(bh * NN + n0) * MF;
#pragma unroll 4
        for (int it = 0; it < 32; it++) {
            int idx = it * 256 + t;         // 0..8191
            int row = idx >> 6;             // 0..127
            int c4 = idx & 63;              // 64 float4 per row
            float4 v = *(const float4*)(kb + (size_t)row * MF + c4 * 4);
            v = kfeat4(v, m);
            __half2 h0 = __floats2half2_rn(v.x, v.y);
            __half2 h1 = __floats2half2_rn(v.z, v.w);
            *(uint2*)(kph + (size_t)row * MF + c4 * 4) =
                make_uint2(*(uint32_t*)&h0, *(uint32_t*)&h1);
        }
    }

    float acc[2][8][4];
#pragma unroll
    for (int i = 0; i < 2; i++)
#pragma unroll
        for (int n = 0; n < 8; n++)
#pragma unroll
            for (int j = 0; j < 4; j++) acc[i][n][j] = 0.f;
    float z0[2] = {0.f, 0.f}, z1[2] = {0.f, 0.f};

    for (int tk = 0; tk < 16; tk++) {
        const int j0 = tk * 8 + tq, j1 = j0 + 4;
        uint32_t af[2][4];
#pragma unroll
        for (int i = 0; i < 2; i++) {
            int mm = (wid * 2 + i) * 16 + g;
            float a0 = kfeat(kb[(size_t)j0 * MF + mm], m);
            float a1 = kfeat(kb[(size_t)j0 * MF + mm + 8], m);
            float a2 = kfeat(kb[(size_t)j1 * MF + mm], m);
            float a3 = kfeat(kb[(size_t)j1 * MF + mm + 8], m);
            z0[i] += a0 + a2;
            z1[i] += a1 + a3;
            af[i][0] = tf32u(a0); af[i][1] = tf32u(a1);
            af[i][2] = tf32u(a2); af[i][3] = tf32u(a3);
        }
#pragma unroll
        for (int nt = 0; nt < 8; nt++) {
            uint32_t bf[2];
            bf[0] = tf32u(vb[(size_t)j0 * Dd + nt * 8 + g]);
            bf[1] = tf32u(vb[(size_t)j1 * Dd + nt * 8 + g]);
            mma16n8k8(acc[0][nt], af[0], bf);
            mma16n8k8(acc[1][nt], af[1], bf);
        }
    }

#pragma unroll
    for (int i = 0; i < 2; i++) {
        z0[i] += __shfl_xor_sync(0xffffffffu, z0[i], 1);
        z0[i] += __shfl_xor_sync(0xffffffffu, z0[i], 2);
        z1[i] += __shfl_xor_sync(0xffffffffu, z1[i], 1);
        z1[i] += __shfl_xor_sync(0xffffffffu, z1[i], 2);
    }
    if (tq == 0) {
        float* zp = g_z + (bh * NC + c) * MF;
#pragma unroll
        for (int i = 0; i < 2; i++) {
            int mm = (wid * 2 + i) * 16 + g;
            zp[mm] = z0[i];
            zp[mm + 8] = z1[i];
        }
    }

    __half* Sp = g_S + (size_t)(bh * NC + c) * MF * DHd;
#pragma unroll
    for (int i = 0; i < 2; i++) {
        int mm = (wid * 2 + i) * 16 + g;
#pragma unroll
        for (int nt = 0; nt < 8; nt++) {
            *(__half2*)(Sp + (size_t)mm * DHd + nt * 8 + tq * 2) =
                __floats2half2_rn(acc[i][nt][0], acc[i][nt][1]);
            *(__half2*)(Sp + (size_t)(mm + 8) * DHd + nt * 8 + tq * 2) =
                __floats2half2_rn(acc[i][nt][2], acc[i][nt][3]);
        }
    }
}

// ---------------------------------------------------------------------------
// Fully parallel exclusive prefix (S as half2, fp32 carry; z fp32)
// ---------------------------------------------------------------------------
__global__ void __launch_bounds__(256) prefix_kernel() {
    const int blk = blockIdx.x;
    if (blk < 1024) {
        int idx = blk * 256 + threadIdx.x;      // 0 .. 262143 (half2 scans)
        int bh = idx >> 13;                     // 8192 half2 per bh-chunk
        int me2 = idx & 8191;
        __half2* base = (__half2*)g_S + (size_t)bh * (NC * 8192) + me2;
        float2 v[NC];
#pragma unroll
        for (int c = 0; c < NC; c++) v[c] = __half22float2(base[(size_t)c * 8192]);
        float2 run = make_float2(0.f, 0.f);
#pragma unroll
        for (int c = 0; c < NC; c++) {
            base[(size_t)c * 8192] = __floats2half2_rn(run.x, run.y);
            run.x += v[c].x;
            run.y += v[c].y;
        }
    } else {
        int bh = blk - 1024;
        int mm = threadIdx.x;
        float* zb = g_z + bh * NC * MF + mm;
        float v[NC];
#pragma unroll
        for (int c = 0; c < NC; c++) v[c] = zb[c * MF];
        float run = 0.f;
#pragma unroll
        for (int c = 0; c < NC; c++) {
            zb[c * MF] = run;
            run += v[c];
        }
    }
}

// ---------------------------------------------------------------------------
// Output kernel: all feature operands half in gmem; per-hf flow is
// stage(Q, K'-both, S) / sync / p1a, p2, p1b (6 syncs total).
// bufA : 64x132 fp32 (Q, later masked A)       = 8448 fl
// bufKh: 128x136 half (K' both chunks)         = 8704 fl-equiv
// bufB1: 128x72 fp32 (S halves / V)            = 9216 fl
// ---------------------------------------------------------------------------
#define PA 132
#define PKH 136   // halves
#define PB1 72
#define OFF_KH 8448
#define OFF_B1 (8448 + 8704)
#define OUT_DSMEM ((8448 + 8704 + 9216) * 4)

__global__ void __launch_bounds__(256, 2) out_kernel(const float* __restrict__ vin,
                                                     float* __restrict__ outp) {
    extern __shared__ float sm[];
    float* bufA = sm;
    __half* bufKh = (__half*)(sm + OFF_KH);
    float* bufB1 = sm + OFF_B1;
    __shared__ float den4[256];
    __shared__ float den[64];
    __shared__ float dinv[64];

    const int t = threadIdx.x, wid = t >> 5, lane = t & 31;
    const int g = lane >> 2, tq = lane & 3;
    const int wm = wid >> 2, wn = wid & 3;
    const int c = blockIdx.x, bh = blockIdx.y, hp = blockIdx.z;
    const int b = bh >> 3, h = bh & 7;
    const int n0 = c * CK;
    const int r0c = hp * 64;
    const int NT1 = hp ? 4 : 2;
    const int NJT = hp ? 16 : 8;
    const int kIters = hp ? 8 : 4;    // V staging float4 iters
    const int kkit = hp ? 8 : 4;      // K' staging uint4 iters (rows/16)

    const __half* qbase = g_qp + (size_t)(bh * NN + n0 + r0c) * MF;
    const __half* kphbase = g_kph + (size_t)(bh * NN + n0) * MF;
    const __half* Sbase = g_S + (size_t)(bh * NC + c) * MF * DHd;
    const float* zg = g_z + (bh * NC + c) * MF;

    // den partial: q . (z_prev + 1e-6), q read as half2
    {
        int i = t >> 2, qq = t & 3;
        float s = 0.f;
        const __half2* qr2 = (const __half2*)(qbase + (size_t)i * MF + qq * 64);
        const float* zr = zg + qq * 64;
#pragma unroll 8
        for (int mm = 0; mm < 32; mm++) {
            float2 qf = __half22float2(qr2[mm]);
            s += qf.x * (zr[2 * mm] + 1e-6f) + qf.y * (zr[2 * mm + 1] + 1e-6f);
        }
        den4[t] = s;
    }

    float accA[2][4][4];
#pragma unroll
    for (int i = 0; i < 2; i++)
#pragma unroll
        for (int j = 0; j < 4; j++)
#pragma unroll
            for (int s = 0; s < 4; s++) accA[i][j][s] = 0.f;
    float acc2[2][2][4];
#pragma unroll
    for (int i = 0; i < 2; i++)
#pragma unroll
        for (int j = 0; j < 2; j++)
#pragma unroll
            for (int s = 0; s < 4; s++) acc2[i][j][s] = 0.f;

#pragma unroll 1
    for (int hf = 0; hf < 2; hf++) {
        if (hf) __syncthreads();
        // Stage Q half hf -> bufA (64 x 128 fp32), source half (exact cvt)
#pragma unroll
        for (int it = 0; it < 4; it++) {
            int idx = it * 256 + t;
            int row = idx >> 4, c8 = idx & 15;
            uint4 u = *(const uint4*)(qbase + (size_t)row * MF + hf * 128 + c8 * 8);
            float2 f0 = __half22float2(*(__half2*)&u.x);
            float2 f1 = __half22float2(*(__half2*)&u.y);
            float2 f2 = __half22float2(*(__half2*)&u.z);
            float2 f3 = __half22float2(*(__half2*)&u.w);
            float* dst = bufA + row * PA + c8 * 8;
            *(float4*)dst = make_float4(f0.x, f0.y, f1.x, f1.y);
            *(float4*)(dst + 4) = make_float4(f2.x, f2.y, f3.x, f3.y);
        }
        // Stage K' both chunks of half hf -> bufKh (raw uint4 copy of halves)
        for (int it = 0; it < kkit; it++) {
            int idx = it * 256 + t;
            int row = idx >> 4, c8 = idx & 15;
            uint4 u = *(const uint4*)(kphbase + (size_t)row * MF + hf * 128 + c8 * 8);
            *(uint4*)(bufKh + row * PKH + c8 * 8) = u;
        }
        // Stage S half hf -> bufB1 (half source, exact cvt to fp32)
#pragma unroll
        for (int it = 0; it < 4; it++) {
            int idx = it * 256 + t;
            int row = idx >> 3, c8 = idx & 7;
            uint4 u = *(const uint4*)(Sbase + (size_t)(hf * 128 + row) * DHd + c8 * 8);
            float2 f0 = __half22float2(*(__half2*)&u.x);
            float2 f1 = __half22float2(*(__half2*)&u.y);
            float2 f2 = __half22float2(*(__half2*)&u.z);
            float2 f3 = __half22float2(*(__half2*)&u.w);
            float* dst = bufB1 + row * PB1 + c8 * 8;
            *(float4*)dst = make_float4(f0.x, f0.y, f1.x, f1.y);
            *(float4*)(dst + 4) = make_float4(f2.x, f2.y, f3.x, f3.y);
        }
        __syncthreads();
        if (hf == 0 && t < 64)
            den[t] = den4[4 * t] + den4[4 * t + 1] + den4[4 * t + 2] + den4[4 * t + 3];

        // Phase 1a: A cols 0..63 x K' cols 0..63
#pragma unroll
        for (int ks = 0; ks < 8; ks++) {
            uint32_t af[2][4];
#pragma unroll
            for (int mt = 0; mt < 2; mt++) {
                const float* ap = bufA + (wm * 32 + mt * 16 + g) * PA + ks * 8 + tq;
                af[mt][0] = __float_as_uint(ap[0]);
                af[mt][1] = __float_as_uint(ap[8 * PA]);
                af[mt][2] = __float_as_uint(ap[4]);
                af[mt][3] = __float_as_uint(ap[8 * PA + 4]);
            }
#pragma unroll
            for (int nt = 0; nt < 4; nt++) {
                if (nt >= NT1) break;
                const __half* bp = bufKh + ((wn * NT1 + nt) * 8 + g) * PKH + ks * 8 + tq;
                uint32_t bf[2] = {__float_as_uint(__half2float(bp[0])),
                                  __float_as_uint(__half2float(bp[4]))};
                mma16n8k8(accA[0][nt], af[0], bf);
                mma16n8k8(accA[1][nt], af[1], bf);
            }
        }
        // Phase 2 (S half hf): K = 128 over bufA cols 0..127
#pragma unroll 2
        for (int ks = 0; ks < 16; ks++) {
            uint32_t af[2][4];
#pragma unroll
            for (int mt = 0; mt < 2; mt++) {
                const float* ap = bufA + (wm * 32 + mt * 16 + g) * PA + ks * 8 + tq;
                af[mt][0] = __float_as_uint(ap[0]);
                af[mt][1] = __float_as_uint(ap[8 * PA]);
                af[mt][2] = __float_as_uint(ap[4]);
                af[mt][3] = __float_as_uint(ap[8 * PA + 4]);
            }
#pragma unroll
            for (int nt = 0; nt < 2; nt++) {
                const float* bp = bufB1 + (ks * 8 + tq) * PB1 + (wn * 2 + nt) * 8 + g;
                uint32_t bf[2] = {__float_as_uint(bp[0]), __float_as_uint(bp[4 * PB1])};
                mma16n8k8(acc2[0][nt], af[0], bf);
                mma16n8k8(acc2[1][nt], af[1], bf);
            }
        }
        // Phase 1b: A cols 64..127 x K' cols 64..127 (no sync needed)
#pragma unroll
        for (int ks = 0; ks < 8; ks++) {
            uint32_t af[2][4];
#pragma unroll
            for (int mt = 0; mt < 2; mt++) {
                const float* ap = bufA + (wm * 32 + mt * 16 + g) * PA + 64 + ks * 8 + tq;
                af[mt][0] = __float_as_uint(ap[0]);
                af[mt][1] = __float_as_uint(ap[8 * PA]);
                af[mt][2] = __float_as_uint(ap[4]);
                af[mt][3] = __float_as_uint(ap[8 * PA + 4]);
            }
#pragma unroll
            for (int nt = 0; nt < 4; nt++) {
                if (nt >= NT1) break;
                const __half* bp = bufKh + ((wn * NT1 + nt) * 8 + g) * PKH + 64 + ks * 8 + tq;
                uint32_t bf[2] = {__float_as_uint(__half2float(bp[0])),
                                  __float_as_uint(__half2float(bp[4]))};
                mma16n8k8(accA[0][nt], af[0], bf);
                mma16n8k8(accA[1][nt], af[1], bf);
            }
        }
    }

    // ---- Mask tril + rowsum -> den ----
#pragma unroll
    for (int mt = 0; mt < 2; mt++) {
        int i0 = wm * 32 + mt * 16 + g;
        int lim0 = r0c + i0, lim1 = lim0 + 8;
        float rs0 = 0.f, rs1 = 0.f;
#pragma unroll
        for (int nt = 0; nt < 4; nt++) {
            if (nt >= NT1) break;
            int cb = (wn * NT1 + nt) * 8 + tq * 2;
            float v0 = (cb     <= lim0) ? accA[mt][nt][0] : 0.f;
            float v1 = (cb + 1 <= lim0) ? accA[mt][nt][1] : 0.f;
            float v2 = (cb     <= lim1) ? accA[mt][nt][2] : 0.f;
            float v3 = (cb + 1 <= lim1) ? accA[mt][nt][3] : 0.f;
            accA[mt][nt][0] = v0; accA[mt][nt][1] = v1;
            accA[mt][nt][2] = v2; accA[mt][nt][3] = v3;
            rs0 += v0 + v1;
            rs1 += v2 + v3;
        }
        rs0 += __shfl_xor_sync(0xffffffffu, rs0, 1);
        rs0 += __shfl_xor_sync(0xffffffffu, rs0, 2);
        rs1 += __shfl_xor_sync(0xffffffffu, rs1, 1);
        rs1 += __shfl_xor_sync(0xffffffffu, rs1, 2);
        if (tq == 0) {
            atomicAdd(&den[i0], rs0);
            atomicAdd(&den[i0 + 8], rs1);
        }
    }
    __syncthreads();

    // ---- dinv; masked A -> bufA; V -> bufB1 ----
    if (t < 64) dinv[t] = 1.0f / den[t];
#pragma unroll
    for (int mt = 0; mt < 2; mt++) {
        int i0 = wm * 32 + mt * 16 + g;
#pragma unroll
        for (int nt = 0; nt < 4; nt++) {
            if (nt >= NT1) break;
            int j = (wn * NT1 + nt) * 8 + tq * 2;
            *(float2*)(bufA + i0 * PA + j) =
                make_float2(tf32r(accA[mt][nt][0]), tf32r(accA[mt][nt][1]));
            *(float2*)(bufA + (i0 + 8) * PA + j) =
                make_float2(tf32r(accA[mt][nt][2]), tf32r(accA[mt][nt][3]));
        }
    }
    for (int it = 0; it < kIters; it++) {
        int idx = it * 256 + t;
        int row = idx >> 4, c4 = idx & 15;
        float4 v = *(const float4*)(vin + ((size_t)(b * NN + n0 + row)) * Dd
                                    + h * DHd + c4 * 4);
        *(float4*)(bufB1 + row * PB1 + c4 * 4) = tf32v4(v);
    }
    __syncthreads();

    // ---- Phase 3: out += tril(A) . V ----
#pragma unroll 2
    for (int ks = 0; ks < 16; ks++) {
        if (ks >= NJT) break;
        uint32_t af[2][4];
#pragma unroll
        for (int mt = 0; mt < 2; mt++) {
            const float* ap = bufA + (wm * 32 + mt * 16 + g) * PA + ks * 8 + tq;
            af[mt][0] = __float_as_uint(ap[0]);
            af[mt][1] = __float_as_uint(ap[8 * PA]);
            af[mt][2] = __float_as_uint(ap[4]);
            af[mt][3] = __float_as_uint(ap[8 * PA + 4]);
        }
#pragma unroll
        for (int nt = 0; nt < 2; nt++) {
            const float* bp = bufB1 + (ks * 8 + tq) * PB1 + (wn * 2 + nt) * 8 + g;
            uint32_t bf[2] = {__float_as_uint(bp[0]), __float_as_uint(bp[4 * PB1])};
            mma16n8k8(acc2[0][nt], af[0], bf);
            mma16n8k8(acc2[1][nt], af[1], bf);
        }
    }

    // ---- Epilogue ----
#pragma unroll
    for (int mt = 0; mt < 2; mt++) {
        int i0 = wm * 32 + mt * 16 + g;
        float d0 = dinv[i0], d1 = dinv[i0 + 8];
        float* op0 = outp + ((size_t)(b * NN + n0 + r0c + i0)) * Dd + h * DHd;
        float* op1 = op0 + (size_t)8 * Dd;
#pragma unroll
        for (int nt = 0; nt < 2; nt++) {
            int e = (wn * 2 + nt) * 8 + tq * 2;
            *(float2*)(op0 + e) = make_float2(acc2[mt][nt][0] * d0,
                                              acc2[mt][nt][1] * d0);
            *(float2*)(op1 + e) = make_float2(acc2[mt][nt][2] * d1,
                                              acc2[mt][nt][3] * d1);
        }
    }
}

// ---------------------------------------------------------------------------
extern "C" void kernel_launch(void* const* d_in, const int* in_sizes, int n_in,
                              void* d_out, int out_size) {
    (void)in_sizes; (void)n_in; (void)out_size;
    const float* q    = (const float*)d_in[0];
    const float* k    = (const float*)d_in[1];
    const float* v    = (const float*)d_in[2];
    const float* proj = (const float*)d_in[3];
    float* out = (float*)d_out;

    cudaFuncSetAttribute(out_kernel, cudaFuncAttributeMaxDynamicSharedMemorySize,
                         OUT_DSMEM);

    feat_kernel<true><<<dim3(32, 32), 256>>>(q, proj);
    feat_kernel<false><<<dim3(32, 32), 256>>>(k, proj);
    chunk_kv_kernel<<<dim3(16, 32), 256>>>(v);
    prefix_kernel<<<1056, 256>>>();
    out_kernel<<<dim3(16, 32, 2), 256, OUT_DSMEM>>>(v, out);
}

// round 13
// speedup vs baseline: 1.0357x; 1.0357x over previous
#include <cuda_runtime.h>
#include <cuda_fp16.h>
#include <math.h>
#include <stdint.h>

// Problem constants
#define Bb 4
#define Hh 8
#define BHn 32
#define NN 2048
#define Dd 512
#define DHd 64
#define MF 256
#define CK 128
#define NC 16

// Scratch
__device__ __align__(16) __half g_qp[(size_t)BHn * NN * MF];  // exp'd q feats (half)
__device__ float g_kp[(size_t)BHn * NN * MF];                 // RAW dd - diag (fp32)
__device__ __align__(16) __half g_S[(size_t)BHn * NC * MF * DHd]; // S (half)
__device__ float g_z [BHn * NC * MF];
__device__ float g_kmax[BHn];

__device__ __forceinline__ float tf32r(float x) {
    uint32_t u = __float_as_uint(x);
    u = (u + 0x1000u) & 0xFFFFE000u;
    return __uint_as_float(u);
}
__device__ __forceinline__ uint32_t tf32u(float x) {
    return (__float_as_uint(x) + 0x1000u) & 0xFFFFE000u;
}
__device__ __forceinline__ float4 tf32v4(float4 v) {
    v.x = tf32r(v.x); v.y = tf32r(v.y); v.z = tf32r(v.z); v.w = tf32r(v.w);
    return v;
}
__device__ __forceinline__ float kfeat(float v, float m) {
    return 0.0625f * (__expf(v - m) + 1e-4f);
}
__device__ __forceinline__ float4 kfeat4(float4 v, float m) {
    v.x = kfeat(v.x, m); v.y = kfeat(v.y, m);
    v.z = kfeat(v.z, m); v.w = kfeat(v.w, m);
    return v;
}

// Warp-level tf32 MMA (portable ISA; tensor pipe)
__device__ __forceinline__ void mma16n8k8(float c[4], const uint32_t a[4],
                                          const uint32_t b[2]) {
    asm volatile(
        "mma.sync.aligned.m16n8k8.row.col.f32.tf32.tf32.f32 "
        "{%0,%1,%2,%3}, {%4,%5,%6,%7}, {%8,%9}, {%0,%1,%2,%3};"
        : "+f"(c[0]), "+f"(c[1]), "+f"(c[2]), "+f"(c[3])
        : "r"(a[0]), "r"(a[1]), "r"(a[2]), "r"(a[3]), "r"(b[0]), "r"(b[1]));
}

// ---------------------------------------------------------------------------
// Feature-map kernel (split-tf32 tensor core; double-buffered proj staging)
// Q output: exp'd half. K output: raw fp32 (dd - diag) + global max.
// ---------------------------------------------------------------------------
template <bool IS_Q>
__global__ void __launch_bounds__(256) feat_kernel(const float* __restrict__ xin,
                                                   const float* __restrict__ proj) {
    __shared__ uint4 ps[2][1024];
    __shared__ float mx[64][2];
    __shared__ float bred[8];

    const int t = threadIdx.x, wid = t >> 5, lane = t & 31;
    const int g = lane >> 2, tq = lane & 3;
    const int wm = wid >> 1, wn = wid & 1;
    const int bh = blockIdx.y, b = bh >> 3, h = bh & 7;
    const int n0 = blockIdx.x * 64;
    const int r0 = n0 + wm * 16;

    if (IS_Q && blockIdx.x == 0 && t == 0) g_kmax[bh] = -1e30f;

    uint4 ah[8], al[8];
    float ss0 = 0.f, ss1 = 0.f;
    const float* xb = xin + ((size_t)b * NN + r0) * Dd + h * DHd;
#pragma unroll
    for (int ks = 0; ks < 8; ks++) {
        float x0 = xb[(size_t)g * Dd + ks * 8 + tq];
        float x1 = xb[(size_t)(g + 8) * Dd + ks * 8 + tq];
        float x2 = xb[(size_t)g * Dd + ks * 8 + tq + 4];
        float x3 = xb[(size_t)(g + 8) * Dd + ks * 8 + tq + 4];
        ss0 += x0 * x0 + x2 * x2;
        ss1 += x1 * x1 + x3 * x3;
        uint32_t h0 = __float_as_uint(x0) & 0xFFFFE000u;
        uint32_t h1 = __float_as_uint(x1) & 0xFFFFE000u;
        uint32_t h2 = __float_as_uint(x2) & 0xFFFFE000u;
        uint32_t h3 = __float_as_uint(x3) & 0xFFFFE000u;
        ah[ks] = make_uint4(h0, h1, h2, h3);
        al[ks] = make_uint4(__float_as_uint(x0 - __uint_as_float(h0)),
                            __float_as_uint(x1 - __uint_as_float(h1)),
                            __float_as_uint(x2 - __uint_as_float(h2)),
                            __float_as_uint(x3 - __uint_as_float(h3)));
    }
    ss0 += __shfl_xor_sync(0xffffffffu, ss0, 1);
    ss0 += __shfl_xor_sync(0xffffffffu, ss0, 2);
    ss1 += __shfl_xor_sync(0xffffffffu, ss1, 1);
    ss1 += __shfl_xor_sync(0xffffffffu, ss1, 2);
    const float diag0 = ss0 * 0.0625f, diag1 = ss1 * 0.0625f;

    float acc[16][4];
#pragma unroll
    for (int i = 0; i < 16; i++)
#pragma unroll
        for (int j = 0; j < 4; j++) acc[i][j] = 0.f;

    // Prologue: stage ks=0 into buffer 0
#pragma unroll
    for (int it = 0; it < 4; it++) {
        int slot = it * 256 + t;
        int nt = slot >> 5, sl = slot & 31;
        int sg = sl >> 2, stq = sl & 3;
        const float* pp = proj + (nt * 8 + sg) * 64 + stq;
        float p0 = pp[0], p1 = pp[4];
        uint32_t h0 = __float_as_uint(p0) & 0xFFFFE000u;
        uint32_t h1 = __float_as_uint(p1) & 0xFFFFE000u;
        ps[0][slot] = make_uint4(h0, h1,
                                 __float_as_uint(p0 - __uint_as_float(h0)),
                                 __float_as_uint(p1 - __uint_as_float(h1)));
    }

    for (int ks = 0; ks < 8; ks++) {
        __syncthreads();
        if (ks < 7) {
            int sks = ks + 1, buf = sks & 1;
#pragma unroll
            for (int it = 0; it < 4; it++) {
                int slot = it * 256 + t;
                int nt = slot >> 5, sl = slot & 31;
                int sg = sl >> 2, stq = sl & 3;
                const float* pp = proj + (nt * 8 + sg) * 64 + sks * 8 + stq;
                float p0 = pp[0], p1 = pp[4];
                uint32_t h0 = __float_as_uint(p0) & 0xFFFFE000u;
                uint32_t h1 = __float_as_uint(p1) & 0xFFFFE000u;
                ps[buf][slot] = make_uint4(h0, h1,
                                           __float_as_uint(p0 - __uint_as_float(h0)),
                                           __float_as_uint(p1 - __uint_as_float(h1)));
            }
        }
        const uint4* pb = ps[ks & 1];
#pragma unroll
        for (int ntl = 0; ntl < 16; ntl++) {
            uint4 pv = pb[(wn * 16 + ntl) * 32 + lane];
            uint32_t bhi[2] = {pv.x, pv.y};
            uint32_t blo[2] = {pv.z, pv.w};
            mma16n8k8(acc[ntl], (const uint32_t*)&ah[ks], bhi);
            mma16n8k8(acc[ntl], (const uint32_t*)&al[ks], bhi);
            mma16n8k8(acc[ntl], (const uint32_t*)&ah[ks], blo);
        }
    }

    const float normalizer = 0.35355339059327373f;
#pragma unroll
    for (int ntl = 0; ntl < 16; ntl++)
#pragma unroll
        for (int j = 0; j < 4; j++) acc[ntl][j] *= normalizer;

    if (IS_Q) {
        float m0 = -1e30f, m1 = -1e30f;
#pragma unroll
        for (int ntl = 0; ntl < 16; ntl++) {
            m0 = fmaxf(m0, fmaxf(acc[ntl][0], acc[ntl][1]));
            m1 = fmaxf(m1, fmaxf(acc[ntl][2], acc[ntl][3]));
        }
        m0 = fmaxf(m0, __shfl_xor_sync(0xffffffffu, m0, 1));
        m0 = fmaxf(m0, __shfl_xor_sync(0xffffffffu, m0, 2));
        m1 = fmaxf(m1, __shfl_xor_sync(0xffffffffu, m1, 1));
        m1 = fmaxf(m1, __shfl_xor_sync(0xffffffffu, m1, 2));
        if (tq == 0) {
            mx[wm * 16 + g][wn] = m0;
            mx[wm * 16 + g + 8][wn] = m1;
        }
        __syncthreads();
        const float M0 = fmaxf(mx[wm * 16 + g][0], mx[wm * 16 + g][1]);
        const float M1 = fmaxf(mx[wm * 16 + g + 8][0], mx[wm * 16 + g + 8][1]);
        __half* o0 = g_qp + ((size_t)bh * NN + r0 + g) * MF + wn * 128;
        __half* o1 = g_qp + ((size_t)bh * NN + r0 + g + 8) * MF + wn * 128;
#pragma unroll
        for (int ntl = 0; ntl < 16; ntl++) {
            float a0 = 0.0625f * (__expf(acc[ntl][0] - diag0 - M0) + 1e-4f);
            float a1 = 0.0625f * (__expf(acc[ntl][1] - diag0 - M0) + 1e-4f);
            float a2 = 0.0625f * (__expf(acc[ntl][2] - diag1 - M1) + 1e-4f);
            float a3 = 0.0625f * (__expf(acc[ntl][3] - diag1 - M1) + 1e-4f);
            *(__half2*)(o0 + ntl * 8 + tq * 2) = __floats2half2_rn(a0, a1);
            *(__half2*)(o1 + ntl * 8 + tq * 2) = __floats2half2_rn(a2, a3);
        }
    } else {
        float km = -1e30f;
        float* o0 = g_kp + ((size_t)bh * NN + r0 + g) * MF + wn * 128;
        float* o1 = g_kp + ((size_t)bh * NN + r0 + g + 8) * MF + wn * 128;
#pragma unroll
        for (int ntl = 0; ntl < 16; ntl++) {
            km = fmaxf(km, fmaxf(fmaxf(acc[ntl][0], acc[ntl][1]),
                                 fmaxf(acc[ntl][2], acc[ntl][3])));
            float2 v0 = make_float2(acc[ntl][0] - diag0, acc[ntl][1] - diag0);
            float2 v1 = make_float2(acc[ntl][2] - diag1, acc[ntl][3] - diag1);
            *(float2*)(o0 + ntl * 8 + tq * 2) = v0;
            *(float2*)(o1 + ntl * 8 + tq * 2) = v1;
        }
#pragma unroll
        for (int off = 16; off; off >>= 1)
            km = fmaxf(km, __shfl_xor_sync(0xffffffffu, km, off));
        if (lane == 0) bred[wid] = km;
        __syncthreads();
        if (t == 0) {
            float m = bred[0];
            for (int w = 1; w < 8; w++) m = fmaxf(m, bred[w]);
            int* addr = (int*)&g_kmax[bh];
            int old = *addr;
            while (__int_as_float(old) < m) {
                int assumed = old;
                old = atomicCAS(addr, assumed, __float_as_int(m));
                if (old == assumed) break;
            }
        }
    }
}

// ---------------------------------------------------------------------------
// Per-chunk local KV state; exp applied on the fly; S written as half.
// ---------------------------------------------------------------------------
__global__ void __launch_bounds__(256) chunk_kv_kernel(const float* __restrict__ vin) {
    const int t = threadIdx.x, wid = t >> 5, lane = t & 31;
    const int g = lane >> 2, tq = lane & 3;
    const int c = blockIdx.x, bh = blockIdx.y;
    const int b = bh >> 3, h = bh & 7;
    const int n0 = c * CK;
    const float* kb = g_kp + (size_t)(bh * NN + n0) * MF;
    const float* vb = vin + ((size_t)(b * NN + n0)) * Dd + h * DHd;
    const float m = g_kmax[bh];

    float acc[2][8][4];
#pragma unroll
    for (int i = 0; i < 2; i++)
#pragma unroll
        for (int n = 0; n < 8; n++)
#pragma unroll
            for (int j = 0; j < 4; j++) acc[i][n][j] = 0.f;
    float z0[2] = {0.f, 0.f}, z1[2] = {0.f, 0.f};

    for (int tk = 0; tk < 16; tk++) {
        const int j0 = tk * 8 + tq, j1 = j0 + 4;
        uint32_t af[2][4];
#pragma unroll
        for (int i = 0; i < 2; i++) {
            int mm = (wid * 2 + i) * 16 + g;
            float a0 = kfeat(kb[(size_t)j0 * MF + mm], m);
            float a1 = kfeat(kb[(size_t)j0 * MF + mm + 8], m);
            float a2 = kfeat(kb[(size_t)j1 * MF + mm], m);
            float a3 = kfeat(kb[(size_t)j1 * MF + mm + 8], m);
            z0[i] += a0 + a2;
            z1[i] += a1 + a3;
            af[i][0] = tf32u(a0); af[i][1] = tf32u(a1);
            af[i][2] = tf32u(a2); af[i][3] = tf32u(a3);
        }
#pragma unroll
        for (int nt = 0; nt < 8; nt++) {
            uint32_t bf[2];
            bf[0] = tf32u(vb[(size_t)j0 * Dd + nt * 8 + g]);
            bf[1] = tf32u(vb[(size_t)j1 * Dd + nt * 8 + g]);
            mma16n8k8(acc[0][nt], af[0], bf);
            mma16n8k8(acc[1][nt], af[1], bf);
        }
    }

#pragma unroll
    for (int i = 0; i < 2; i++) {
        z0[i] += __shfl_xor_sync(0xffffffffu, z0[i], 1);
        z0[i] += __shfl_xor_sync(0xffffffffu, z0[i], 2);
        z1[i] += __shfl_xor_sync(0xffffffffu, z1[i], 1);
        z1[i] += __shfl_xor_sync(0xffffffffu, z1[i], 2);
    }
    if (tq == 0) {
        float* zp = g_z + (bh * NC + c) * MF;
#pragma unroll
        for (int i = 0; i < 2; i++) {
            int mm = (wid * 2 + i) * 16 + g;
            zp[mm] = z0[i];
            zp[mm + 8] = z1[i];
        }
    }

    __half* Sp = g_S + (size_t)(bh * NC + c) * MF * DHd;
#pragma unroll
    for (int i = 0; i < 2; i++) {
        int mm = (wid * 2 + i) * 16 + g;
#pragma unroll
        for (int nt = 0; nt < 8; nt++) {
            *(__half2*)(Sp + (size_t)mm * DHd + nt * 8 + tq * 2) =
                __floats2half2_rn(acc[i][nt][0], acc[i][nt][1]);
            *(__half2*)(Sp + (size_t)(mm + 8) * DHd + nt * 8 + tq * 2) =
                __floats2half2_rn(acc[i][nt][2], acc[i][nt][3]);
        }
    }
}

// ---------------------------------------------------------------------------
// Fully parallel exclusive prefix (S as half2, fp32 carry; z fp32)
// ---------------------------------------------------------------------------
__global__ void __launch_bounds__(256) prefix_kernel() {
    const int blk = blockIdx.x;
    if (blk < 1024) {
        int idx = blk * 256 + threadIdx.x;      // half2 scans
        int bh = idx >> 13;                     // 8192 half2 per bh
        int me2 = idx & 8191;
        __half2* base = (__half2*)g_S + (size_t)bh * (NC * 8192) + me2;
        float2 v[NC];
#pragma unroll
        for (int c = 0; c < NC; c++) v[c] = __half22float2(base[(size_t)c * 8192]);
        float2 run = make_float2(0.f, 0.f);
#pragma unroll
        for (int c = 0; c < NC; c++) {
            base[(size_t)c * 8192] = __floats2half2_rn(run.x, run.y);
            run.x += v[c].x;
            run.y += v[c].y;
        }
    } else {
        int bh = blk - 1024;
        int mm = threadIdx.x;
        float* zb = g_z + bh * NC * MF + mm;
        float v[NC];
#pragma unroll
        for (int c = 0; c < NC; c++) v[c] = zb[c * MF];
        float run = 0.f;
#pragma unroll
        for (int c = 0; c < NC; c++) {
            zb[c * MF] = run;
            run += v[c];
        }
    }
}

// ---------------------------------------------------------------------------
// Output kernel: round-11 structure; S staged from half (exact cvt).
// bufA : 64x132 fp32 (Q, later masked A)       = 8448 fl
// bufKh: 128x136 half (K' both chunks, exp'd)  = 8704 fl-equiv
// bufB1: 128x72 fp32 (S halves / V)            = 9216 fl
// ---------------------------------------------------------------------------
#define PA 132
#define PKH 136   // halves
#define PB1 72
#define OFF_KH 8448
#define OFF_B1 (8448 + 8704)
#define OUT_DSMEM ((8448 + 8704 + 9216) * 4)

__global__ void __launch_bounds__(256, 2) out_kernel(const float* __restrict__ vin,
                                                     float* __restrict__ outp) {
    extern __shared__ float sm[];
    float* bufA = sm;
    __half* bufKh = (__half*)(sm + OFF_KH);
    float* bufB1 = sm + OFF_B1;
    __shared__ float den4[256];
    __shared__ float den[64];
    __shared__ float dinv[64];

    const int t = threadIdx.x, wid = t >> 5, lane = t & 31;
    const int g = lane >> 2, tq = lane & 3;
    const int wm = wid >> 2, wn = wid & 3;
    const int c = blockIdx.x, bh = blockIdx.y, hp = blockIdx.z;
    const int b = bh >> 3, h = bh & 7;
    const int n0 = c * CK;
    const int r0c = hp * 64;
    const int NT1 = hp ? 4 : 2;
    const int NJT = hp ? 16 : 8;
    const int kIters = hp ? 8 : 4;    // V staging float4 iters
    const int kit2 = hp ? 16 : 8;     // K staging float4 iters (128 cols)

    const __half* qbase = g_qp + (size_t)(bh * NN + n0 + r0c) * MF;
    const float* kbase = g_kp + (size_t)(bh * NN + n0) * MF;
    const __half* Sbase = g_S + (size_t)(bh * NC + c) * MF * DHd;
    const float* zg = g_z + (bh * NC + c) * MF;
    const float kmaxv = g_kmax[bh];

    // den partial: q . (z_prev + 1e-6), q read as half2
    {
        int i = t >> 2, qq = t & 3;
        float s = 0.f;
        const __half2* qr2 = (const __half2*)(qbase + (size_t)i * MF + qq * 64);
        const float* zr = zg + qq * 64;
#pragma unroll 8
        for (int mm = 0; mm < 32; mm++) {
            float2 qf = __half22float2(qr2[mm]);
            s += qf.x * (zr[2 * mm] + 1e-6f) + qf.y * (zr[2 * mm + 1] + 1e-6f);
        }
        den4[t] = s;
    }

    float accA[2][4][4];
#pragma unroll
    for (int i = 0; i < 2; i++)
#pragma unroll
        for (int j = 0; j < 4; j++)
#pragma unroll
            for (int s = 0; s < 4; s++) accA[i][j][s] = 0.f;
    float acc2[2][2][4];
#pragma unroll
    for (int i = 0; i < 2; i++)
#pragma unroll
        for (int j = 0; j < 2; j++)
#pragma unroll
            for (int s = 0; s < 4; s++) acc2[i][j][s] = 0.f;

#pragma unroll 1
    for (int hf = 0; hf < 2; hf++) {
        if (hf) __syncthreads();
        // Stage Q half hf -> bufA (64 x 128 fp32), source half (exact cvt)
#pragma unroll
        for (int it = 0; it < 4; it++) {
            int idx = it * 256 + t;
            int row = idx >> 4, c8 = idx & 15;
            uint4 u = *(const uint4*)(qbase + (size_t)row * MF + hf * 128 + c8 * 8);
            float2 f0 = __half22float2(*(__half2*)&u.x);
            float2 f1 = __half22float2(*(__half2*)&u.y);
            float2 f2 = __half22float2(*(__half2*)&u.z);
            float2 f3 = __half22float2(*(__half2*)&u.w);
            float* dst = bufA + row * PA + c8 * 8;
            *(float4*)dst = make_float4(f0.x, f0.y, f1.x, f1.y);
            *(float4*)(dst + 4) = make_float4(f2.x, f2.y, f3.x, f3.y);
        }
        // Stage K' BOTH chunks of half hf -> bufKh (exp'd, half)
        for (int it = 0; it < kit2; it++) {
            int idx = it * 256 + t;
            int row = idx >> 5, c4 = idx & 31;
            float4 v = *(const float4*)(kbase + (size_t)row * MF + hf * 128 + c4 * 4);
            v = kfeat4(v, kmaxv);
            __half2 h0 = __floats2half2_rn(v.x, v.y);
            __half2 h1 = __floats2half2_rn(v.z, v.w);
            *(uint2*)(bufKh + row * PKH + c4 * 4) =
                make_uint2(*(uint32_t*)&h0, *(uint32_t*)&h1);
        }
        // Stage S half hf -> bufB1 (half source, exact cvt to fp32)
#pragma unroll
        for (int it = 0; it < 4; it++) {
            int idx = it * 256 + t;
            int row = idx >> 3, c8 = idx & 7;
            uint4 u = *(const uint4*)(Sbase + (size_t)(hf * 128 + row) * DHd + c8 * 8);
            float2 f0 = __half22float2(*(__half2*)&u.x);
            float2 f1 = __half22float2(*(__half2*)&u.y);
            float2 f2 = __half22float2(*(__half2*)&u.z);
            float2 f3 = __half22float2(*(__half2*)&u.w);
            float* dst = bufB1 + row * PB1 + c8 * 8;
            *(float4*)dst = make_float4(f0.x, f0.y, f1.x, f1.y);
            *(float4*)(dst + 4) = make_float4(f2.x, f2.y, f3.x, f3.y);
        }
        __syncthreads();
        if (hf == 0 && t < 64)
            den[t] = den4[4 * t] + den4[4 * t + 1] + den4[4 * t + 2] + den4[4 * t + 3];

        // Phase 1a: A cols 0..63 x K' cols 0..63
#pragma unroll
        for (int ks = 0; ks < 8; ks++) {
            uint32_t af[2][4];
#pragma unroll
            for (int mt = 0; mt < 2; mt++) {
                const float* ap = bufA + (wm * 32 + mt * 16 + g) * PA + ks * 8 + tq;
                af[mt][0] = __float_as_uint(ap[0]);
                af[mt][1] = __float_as_uint(ap[8 * PA]);
                af[mt][2] = __float_as_uint(ap[4]);
                af[mt][3] = __float_as_uint(ap[8 * PA + 4]);
            }
#pragma unroll
            for (int nt = 0; nt < 4; nt++) {
                if (nt >= NT1) break;
                const __half* bp = bufKh + ((wn * NT1 + nt) * 8 + g) * PKH + ks * 8 + tq;
                uint32_t bf[2] = {__float_as_uint(__half2float(bp[0])),
                                  __float_as_uint(__half2float(bp[4]))};
                mma16n8k8(accA[0][nt], af[0], bf);
                mma16n8k8(accA[1][nt], af[1], bf);
            }
        }
        // Phase 2 (S half hf): K = 128 over bufA cols 0..127
#pragma unroll 2
        for (int ks = 0; ks < 16; ks++) {
            uint32_t af[2][4];
#pragma unroll
            for (int mt = 0; mt < 2; mt++) {
                const float* ap = bufA + (wm * 32 + mt * 16 + g) * PA + ks * 8 + tq;
                af[mt][0] = __float_as_uint(ap[0]);
                af[mt][1] = __float_as_uint(ap[8 * PA]);
                af[mt][2] = __float_as_uint(ap[4]);
                af[mt][3] = __float_as_uint(ap[8 * PA + 4]);
            }
#pragma unroll
            for (int nt = 0; nt < 2; nt++) {
                const float* bp = bufB1 + (ks * 8 + tq) * PB1 + (wn * 2 + nt) * 8 + g;
                uint32_t bf[2] = {__float_as_uint(bp[0]), __float_as_uint(bp[4 * PB1])};
                mma16n8k8(acc2[0][nt], af[0], bf);
                mma16n8k8(acc2[1][nt], af[1], bf);
            }
        }
        // Phase 1b: A cols 64..127 x K' cols 64..127 (no sync needed)
#pragma unroll
        for (int ks = 0; ks < 8; ks++) {
            uint32_t af[2][4];
#pragma unroll
            for (int mt = 0; mt < 2; mt++) {
                const float* ap = bufA + (wm * 32 + mt * 16 + g) * PA + 64 + ks * 8 + tq;
                af[mt][0] = __float_as_uint(ap[0]);
                af[mt][1] = __float_as_uint(ap[8 * PA]);
                af[mt][2] = __float_as_uint(ap[4]);
                af[mt][3] = __float_as_uint(ap[8 * PA + 4]);
            }
#pragma unroll
            for (int nt = 0; nt < 4; nt++) {
                if (nt >= NT1) break;
                const __half* bp = bufKh + ((wn * NT1 + nt) * 8 + g) * PKH + 64 + ks * 8 + tq;
                uint32_t bf[2] = {__float_as_uint(__half2float(bp[0])),
                                  __float_as_uint(__half2float(bp[4]))};
                mma16n8k8(accA[0][nt], af[0], bf);
                mma16n8k8(accA[1][nt], af[1], bf);
            }
        }
    }

    // ---- Mask tril + rowsum -> den ----
#pragma unroll
    for (int mt = 0; mt < 2; mt++) {
        int i0 = wm * 32 + mt * 16 + g;
        int lim0 = r0c + i0, lim1 = lim0 + 8;
        float rs0 = 0.f, rs1 = 0.f;
#pragma unroll
        for (int nt = 0; nt < 4; nt++) {
            if (nt >= NT1) break;
            int cb = (wn * NT1 + nt) * 8 + tq * 2;
            float v0 = (cb     <= lim0) ? accA[mt][nt][0] : 0.f;
            float v1 = (cb + 1 <= lim0) ? accA[mt][nt][1] : 0.f;
            float v2 = (cb     <= lim1) ? accA[mt][nt][2] : 0.f;
            float v3 = (cb + 1 <= lim1) ? accA[mt][nt][3] : 0.f;
            accA[mt][nt][0] = v0; accA[mt][nt][1] = v1;
            accA[mt][nt][2] = v2; accA[mt][nt][3] = v3;
            rs0 += v0 + v1;
            rs1 += v2 + v3;
        }
        rs0 += __shfl_xor_sync(0xffffffffu, rs0, 1);
        rs0 += __shfl_xor_sync(0xffffffffu, rs0, 2);
        rs1 += __shfl_xor_sync(0xffffffffu, rs1, 1);
        rs1 += __shfl_xor_sync(0xffffffffu, rs1, 2);
        if (tq == 0) {
            atomicAdd(&den[i0], rs0);
            atomicAdd(&den[i0 + 8], rs1);
        }
    }
    __syncthreads();

    // ---- dinv; masked A -> bufA; V -> bufB1 ----
    if (t < 64) dinv[t] = 1.0f / den[t];
#pragma unroll
    for (int mt = 0; mt < 2; mt++) {
        int i0 = wm * 32 + mt * 16 + g;
#pragma unroll
        for (int nt = 0; nt < 4; nt++) {
            if (nt >= NT1) break;
            int j = (wn * NT1 + nt) * 8 + tq * 2;
            *(float2*)(bufA + i0 * PA + j) =
                make_float2(tf32r(accA[mt][nt][0]), tf32r(accA[mt][nt][1]));
            *(float2*)(bufA + (i0 + 8) * PA + j) =
                make_float2(tf32r(accA[mt][nt][2]), tf32r(accA[mt][nt][3]));
        }
    }
    for (int it = 0; it < kIters; it++) {
        int idx = it * 256 + t;
        int row = idx >> 4, c4 = idx & 15;
        float4 v = *(const float4*)(vin + ((size_t)(b * NN + n0 + row)) * Dd
                                    + h * DHd + c4 * 4);
        *(float4*)(bufB1 + row * PB1 + c4 * 4) = tf32v4(v);
    }
    __syncthreads();

    // ---- Phase 3: out += tril(A) . V ----
#pragma unroll 2
    for (int ks = 0; ks < 16; ks++) {
        if (ks >= NJT) break;
        uint32_t af[2][4];
#pragma unroll
        for (int mt = 0; mt < 2; mt++) {
            const float* ap = bufA + (wm * 32 + mt * 16 + g) * PA + ks * 8 + tq;
            af[mt][0] = __float_as_uint(ap[0]);
            af[mt][1] = __float_as_uint(ap[8 * PA]);
            af[mt][2] = __float_as_uint(ap[4]);
            af[mt][3] = __float_as_uint(ap[8 * PA + 4]);
        }
#pragma unroll
        for (int nt = 0; nt < 2; nt++) {
            const float* bp = bufB1 + (ks * 8 + tq) * PB1 + (wn * 2 + nt) * 8 + g;
            uint32_t bf[2] = {__float_as_uint(bp[0]), __float_as_uint(bp[4 * PB1])};
            mma16n8k8(acc2[0][nt], af[0], bf);
            mma16n8k8(acc2[1][nt], af[1], bf);
        }
    }

    // ---- Epilogue ----
#pragma unroll
    for (int mt = 0; mt < 2; mt++) {
        int i0 = wm * 32 + mt * 16 + g;
        float d0 = dinv[i0], d1 = dinv[i0 + 8];
        float* op0 = outp + ((size_t)(b * NN + n0 + r0c + i0)) * Dd + h * DHd;
        float* op1 = op0 + (size_t)8 * Dd;
#pragma unroll
        for (int nt = 0; nt < 2; nt++) {
            int e = (wn * 2 + nt) * 8 + tq * 2;
            *(float2*)(op0 + e) = make_float2(acc2[mt][nt][0] * d0,
                                              acc2[mt][nt][1] * d0);
            *(float2*)(op1 + e) = make_float2(acc2[mt][nt][2] * d1,
                                              acc2[mt][nt][3] * d1);
        }
    }
}

// ---------------------------------------------------------------------------
extern "C" void kernel_launch(void* const* d_in, const int* in_sizes, int n_in,
                              void* d_out, int out_size) {
    (void)in_sizes; (void)n_in; (void)out_size;
    const float* q    = (const float*)d_in[0];
    const float* k    = (const float*)d_in[1];
    const float* v    = (const float*)d_in[2];
    const float* proj = (const float*)d_in[3];
    float* out = (float*)d_out;

    cudaFuncSetAttribute(out_kernel, cudaFuncAttributeMaxDynamicSharedMemorySize,
                         OUT_DSMEM);

    feat_kernel<true><<<dim3(32, 32), 256>>>(q, proj);
    feat_kernel<false><<<dim3(32, 32), 256>>>(k, proj);
    chunk_kv_kernel<<<dim3(16, 32), 256>>>(v);
    prefix_kernel<<<1056, 256>>>();
    out_kernel<<<dim3(16, 32, 2), 256, OUT_DSMEM>>>(v, out);
}

// round 14
// speedup vs baseline: 1.2351x; 1.1925x over previous
#include <cuda_runtime.h>
#include <cuda_fp16.h>
#include <math.h>
#include <stdint.h>

// Problem constants
#define Bb 4
#define Hh 8
#define BHn 32
#define NN 2048
#define Dd 512
#define DHd 64
#define MF 256
#define CK 128
#define NC 16

// Scratch
__device__ __align__(16) __half g_qp[(size_t)BHn * NN * MF];   // exp'd q feats (half)
__device__ __align__(16) __half g_kph[(size_t)BHn * NN * MF];  // exp(dd-diag-m_blk) (half)
__device__ __align__(16) __half g_S[(size_t)BHn * NC * MF * DHd]; // S (half)
__device__ float g_z [BHn * NC * MF];
__device__ float g_kmax[BHn];
__device__ float g_mblk[BHn * 32];   // per-64-row-block max of dd

__device__ __forceinline__ float tf32r(float x) {
    uint32_t u = __float_as_uint(x);
    u = (u + 0x1000u) & 0xFFFFE000u;
    return __uint_as_float(u);
}
__device__ __forceinline__ uint32_t tf32u(float x) {
    return (__float_as_uint(x) + 0x1000u) & 0xFFFFE000u;
}
__device__ __forceinline__ float4 tf32v4(float4 v) {
    v.x = tf32r(v.x); v.y = tf32r(v.y); v.z = tf32r(v.z); v.w = tf32r(v.w);
    return v;
}

// Warp-level tf32 MMA (portable ISA; tensor pipe)
__device__ __forceinline__ void mma16n8k8(float c[4], const uint32_t a[4],
                                          const uint32_t b[2]) {
    asm volatile(
        "mma.sync.aligned.m16n8k8.row.col.f32.tf32.tf32.f32 "
        "{%0,%1,%2,%3}, {%4,%5,%6,%7}, {%8,%9}, {%0,%1,%2,%3};"
        : "+f"(c[0]), "+f"(c[1]), "+f"(c[2]), "+f"(c[3])
        : "r"(a[0]), "r"(a[1]), "r"(a[2]), "r"(a[3]), "r"(b[0]), "r"(b[1]));
}

// ---------------------------------------------------------------------------
// Feature-map kernel (split-tf32 tensor core; double-buffered proj staging)
// Q: exp'd half. K: block-scaled exp'd half + per-block max + global max.
// ---------------------------------------------------------------------------
template <bool IS_Q>
__global__ void __launch_bounds__(256) feat_kernel(const float* __restrict__ xin,
                                                   const float* __restrict__ proj) {
    __shared__ uint4 ps[2][1024];
    __shared__ float mx[64][2];
    __shared__ float bred[8];

    const int t = threadIdx.x, wid = t >> 5, lane = t & 31;
    const int g = lane >> 2, tq = lane & 3;
    const int wm = wid >> 1, wn = wid & 1;
    const int bh = blockIdx.y, b = bh >> 3, h = bh & 7;
    const int n0 = blockIdx.x * 64;
    const int r0 = n0 + wm * 16;

    if (IS_Q && blockIdx.x == 0 && t == 0) g_kmax[bh] = -1e30f;

    uint4 ah[8], al[8];
    float ss0 = 0.f, ss1 = 0.f;
    const float* xb = xin + ((size_t)b * NN + r0) * Dd + h * DHd;
#pragma unroll
    for (int ks = 0; ks < 8; ks++) {
        float x0 = xb[(size_t)g * Dd + ks * 8 + tq];
        float x1 = xb[(size_t)(g + 8) * Dd + ks * 8 + tq];
        float x2 = xb[(size_t)g * Dd + ks * 8 + tq + 4];
        float x3 = xb[(size_t)(g + 8) * Dd + ks * 8 + tq + 4];
        ss0 += x0 * x0 + x2 * x2;
        ss1 += x1 * x1 + x3 * x3;
        uint32_t h0 = __float_as_uint(x0) & 0xFFFFE000u;
        uint32_t h1 = __float_as_uint(x1) & 0xFFFFE000u;
        uint32_t h2 = __float_as_uint(x2) & 0xFFFFE000u;
        uint32_t h3 = __float_as_uint(x3) & 0xFFFFE000u;
        ah[ks] = make_uint4(h0, h1, h2, h3);
        al[ks] = make_uint4(__float_as_uint(x0 - __uint_as_float(h0)),
                            __float_as_uint(x1 - __uint_as_float(h1)),
                            __float_as_uint(x2 - __uint_as_float(h2)),
                            __float_as_uint(x3 - __uint_as_float(h3)));
    }
    ss0 += __shfl_xor_sync(0xffffffffu, ss0, 1);
    ss0 += __shfl_xor_sync(0xffffffffu, ss0, 2);
    ss1 += __shfl_xor_sync(0xffffffffu, ss1, 1);
    ss1 += __shfl_xor_sync(0xffffffffu, ss1, 2);
    const float diag0 = ss0 * 0.0625f, diag1 = ss1 * 0.0625f;

    float acc[16][4];
#pragma unroll
    for (int i = 0; i < 16; i++)
#pragma unroll
        for (int j = 0; j < 4; j++) acc[i][j] = 0.f;

    // Prologue: stage ks=0 into buffer 0
#pragma unroll
    for (int it = 0; it < 4; it++) {
        int slot = it * 256 + t;
        int nt = slot >> 5, sl = slot & 31;
        int sg = sl >> 2, stq = sl & 3;
        const float* pp = proj + (nt * 8 + sg) * 64 + stq;
        float p0 = pp[0], p1 = pp[4];
        uint32_t h0 = __float_as_uint(p0) & 0xFFFFE000u;
        uint32_t h1 = __float_as_uint(p1) & 0xFFFFE000u;
        ps[0][slot] = make_uint4(h0, h1,
                                 __float_as_uint(p0 - __uint_as_float(h0)),
                                 __float_as_uint(p1 - __uint_as_float(h1)));
    }

    for (int ks = 0; ks < 8; ks++) {
        __syncthreads();
        if (ks < 7) {
            int sks = ks + 1, buf = sks & 1;
#pragma unroll
            for (int it = 0; it < 4; it++) {
                int slot = it * 256 + t;
                int nt = slot >> 5, sl = slot & 31;
                int sg = sl >> 2, stq = sl & 3;
                const float* pp = proj + (nt * 8 + sg) * 64 + sks * 8 + stq;
                float p0 = pp[0], p1 = pp[4];
                uint32_t h0 = __float_as_uint(p0) & 0xFFFFE000u;
                uint32_t h1 = __float_as_uint(p1) & 0xFFFFE000u;
                ps[buf][slot] = make_uint4(h0, h1,
                                           __float_as_uint(p0 - __uint_as_float(h0)),
                                           __float_as_uint(p1 - __uint_as_float(h1)));
            }
        }
        const uint4* pb = ps[ks & 1];
#pragma unroll
        for (int ntl = 0; ntl < 16; ntl++) {
            uint4 pv = pb[(wn * 16 + ntl) * 32 + lane];
            uint32_t bhi[2] = {pv.x, pv.y};
            uint32_t blo[2] = {pv.z, pv.w};
            mma16n8k8(acc[ntl], (const uint32_t*)&ah[ks], bhi);
            mma16n8k8(acc[ntl], (const uint32_t*)&al[ks], bhi);
            mma16n8k8(acc[ntl], (const uint32_t*)&ah[ks], blo);
        }
    }

    const float normalizer = 0.35355339059327373f;
#pragma unroll
    for (int ntl = 0; ntl < 16; ntl++)
#pragma unroll
        for (int j = 0; j < 4; j++) acc[ntl][j] *= normalizer;

    if (IS_Q) {
        float m0 = -1e30f, m1 = -1e30f;
#pragma unroll
        for (int ntl = 0; ntl < 16; ntl++) {
            m0 = fmaxf(m0, fmaxf(acc[ntl][0], acc[ntl][1]));
            m1 = fmaxf(m1, fmaxf(acc[ntl][2], acc[ntl][3]));
        }
        m0 = fmaxf(m0, __shfl_xor_sync(0xffffffffu, m0, 1));
        m0 = fmaxf(m0, __shfl_xor_sync(0xffffffffu, m0, 2));
        m1 = fmaxf(m1, __shfl_xor_sync(0xffffffffu, m1, 1));
        m1 = fmaxf(m1, __shfl_xor_sync(0xffffffffu, m1, 2));
        if (tq == 0) {
            mx[wm * 16 + g][wn] = m0;
            mx[wm * 16 + g + 8][wn] = m1;
        }
        __syncthreads();
        const float M0 = fmaxf(mx[wm * 16 + g][0], mx[wm * 16 + g][1]);
        const float M1 = fmaxf(mx[wm * 16 + g + 8][0], mx[wm * 16 + g + 8][1]);
        __half* o0 = g_qp + ((size_t)bh * NN + r0 + g) * MF + wn * 128;
        __half* o1 = g_qp + ((size_t)bh * NN + r0 + g + 8) * MF + wn * 128;
#pragma unroll
        for (int ntl = 0; ntl < 16; ntl++) {
            float a0 = 0.0625f * (__expf(acc[ntl][0] - diag0 - M0) + 1e-4f);
            float a1 = 0.0625f * (__expf(acc[ntl][1] - diag0 - M0) + 1e-4f);
            float a2 = 0.0625f * (__expf(acc[ntl][2] - diag1 - M1) + 1e-4f);
            float a3 = 0.0625f * (__expf(acc[ntl][3] - diag1 - M1) + 1e-4f);
            *(__half2*)(o0 + ntl * 8 + tq * 2) = __floats2half2_rn(a0, a1);
            *(__half2*)(o1 + ntl * 8 + tq * 2) = __floats2half2_rn(a2, a3);
        }
    } else {
        // block max of dd
        float km = -1e30f;
#pragma unroll
        for (int ntl = 0; ntl < 16; ntl++) {
            km = fmaxf(km, fmaxf(fmaxf(acc[ntl][0], acc[ntl][1]),
                                 fmaxf(acc[ntl][2], acc[ntl][3])));
        }
#pragma unroll
        for (int off = 16; off; off >>= 1)
            km = fmaxf(km, __shfl_xor_sync(0xffffffffu, km, off));
        if (lane == 0) bred[wid] = km;
        __syncthreads();
        float mblk = bred[0];
#pragma unroll
        for (int w = 1; w < 8; w++) mblk = fmaxf(mblk, bred[w]);

        __half* o0 = g_kph + ((size_t)bh * NN + r0 + g) * MF + wn * 128;
        __half* o1 = g_kph + ((size_t)bh * NN + r0 + g + 8) * MF + wn * 128;
#pragma unroll
        for (int ntl = 0; ntl < 16; ntl++) {
            float e0 = __expf(acc[ntl][0] - diag0 - mblk);
            float e1 = __expf(acc[ntl][1] - diag0 - mblk);
            float e2 = __expf(acc[ntl][2] - diag1 - mblk);
            float e3 = __expf(acc[ntl][3] - diag1 - mblk);
            *(__half2*)(o0 + ntl * 8 + tq * 2) = __floats2half2_rn(e0, e1);
            *(__half2*)(o1 + ntl * 8 + tq * 2) = __floats2half2_rn(e2, e3);
        }
        if (t == 0) {
            g_mblk[bh * 32 + blockIdx.x] = mblk;
            int* addr = (int*)&g_kmax[bh];
            int old = *addr;
            while (__int_as_float(old) < mblk) {
                int assumed = old;
                old = atomicCAS(addr, assumed, __float_as_int(mblk));
                if (old == assumed) break;
            }
        }
    }
}

// ---------------------------------------------------------------------------
// Per-chunk local KV state; k' from block-scaled half (no MUFU); S half out.
// ---------------------------------------------------------------------------
__global__ void __launch_bounds__(256) chunk_kv_kernel(const float* __restrict__ vin) {
    const int t = threadIdx.x, wid = t >> 5, lane = t & 31;
    const int g = lane >> 2, tq = lane & 3;
    const int c = blockIdx.x, bh = blockIdx.y;
    const int b = bh >> 3, h = bh & 7;
    const int n0 = c * CK;
    const __half* kb = g_kph + (size_t)(bh * NN + n0) * MF;
    const float* vb = vin + ((size_t)(b * NN + n0)) * Dd + h * DHd;
    const float m = g_kmax[bh];
    const float s0 = __expf(g_mblk[bh * 32 + 2 * c] - m);       // rows 0..63
    const float s1 = __expf(g_mblk[bh * 32 + 2 * c + 1] - m);   // rows 64..127

    float acc[2][8][4];
#pragma unroll
    for (int i = 0; i < 2; i++)
#pragma unroll
        for (int n = 0; n < 8; n++)
#pragma unroll
            for (int j = 0; j < 4; j++) acc[i][n][j] = 0.f;
    float z0[2] = {0.f, 0.f}, z1[2] = {0.f, 0.f};

    for (int tk = 0; tk < 16; tk++) {
        const int j0 = tk * 8 + tq, j1 = j0 + 4;
        const float sA = (tk < 8) ? s0 : s1;
        uint32_t af[2][4];
#pragma unroll
        for (int i = 0; i < 2; i++) {
            int mm = (wid * 2 + i) * 16 + g;
            float a0 = 0.0625f * (__half2float(kb[(size_t)j0 * MF + mm]) * sA + 1e-4f);
            float a1 = 0.0625f * (__half2float(kb[(size_t)j0 * MF + mm + 8]) * sA + 1e-4f);
            float a2 = 0.0625f * (__half2float(kb[(size_t)j1 * MF + mm]) * sA + 1e-4f);
            float a3 = 0.0625f * (__half2float(kb[(size_t)j1 * MF + mm + 8]) * sA + 1e-4f);
            z0[i] += a0 + a2;
            z1[i] += a1 + a3;
            af[i][0] = tf32u(a0); af[i][1] = tf32u(a1);
            af[i][2] = tf32u(a2); af[i][3] = tf32u(a3);
        }
#pragma unroll
        for (int nt = 0; nt < 8; nt++) {
            uint32_t bf[2];
            bf[0] = tf32u(vb[(size_t)j0 * Dd + nt * 8 + g]);
            bf[1] = tf32u(vb[(size_t)j1 * Dd + nt * 8 + g]);
            mma16n8k8(acc[0][nt], af[0], bf);
            mma16n8k8(acc[1][nt], af[1], bf);
        }
    }

#pragma unroll
    for (int i = 0; i < 2; i++) {
        z0[i] += __shfl_xor_sync(0xffffffffu, z0[i], 1);
        z0[i] += __shfl_xor_sync(0xffffffffu, z0[i], 2);
        z1[i] += __shfl_xor_sync(0xffffffffu, z1[i], 1);
        z1[i] += __shfl_xor_sync(0xffffffffu, z1[i], 2);
    }
    if (tq == 0) {
        float* zp = g_z + (bh * NC + c) * MF;
#pragma unroll
        for (int i = 0; i < 2; i++) {
            int mm = (wid * 2 + i) * 16 + g;
            zp[mm] = z0[i];
            zp[mm + 8] = z1[i];
        }
    }

    __half* Sp = g_S + (size_t)(bh * NC + c) * MF * DHd;
#pragma unroll
    for (int i = 0; i < 2; i++) {
        int mm = (wid * 2 + i) * 16 + g;
#pragma unroll
        for (int nt = 0; nt < 8; nt++) {
            *(__half2*)(Sp + (size_t)mm * DHd + nt * 8 + tq * 2) =
                __floats2half2_rn(acc[i][nt][0], acc[i][nt][1]);
            *(__half2*)(Sp + (size_t)(mm + 8) * DHd + nt * 8 + tq * 2) =
                __floats2half2_rn(acc[i][nt][2], acc[i][nt][3]);
        }
    }
}

// ---------------------------------------------------------------------------
// Fully parallel exclusive prefix (S as half2, fp32 carry; z fp32)
// ---------------------------------------------------------------------------
__global__ void __launch_bounds__(256) prefix_kernel() {
    const int blk = blockIdx.x;
    if (blk < 1024) {
        int idx = blk * 256 + threadIdx.x;
        int bh = idx >> 13;
        int me2 = idx & 8191;
        __half2* base = (__half2*)g_S + (size_t)bh * (NC * 8192) + me2;
        float2 v[NC];
#pragma unroll
        for (int c = 0; c < NC; c++) v[c] = __half22float2(base[(size_t)c * 8192]);
        float2 run = make_float2(0.f, 0.f);
#pragma unroll
        for (int c = 0; c < NC; c++) {
            base[(size_t)c * 8192] = __floats2half2_rn(run.x, run.y);
            run.x += v[c].x;
            run.y += v[c].y;
        }
    } else {
        int bh = blk - 1024;
        int mm = threadIdx.x;
        float* zb = g_z + bh * NC * MF + mm;
        float v[NC];
#pragma unroll
        for (int c = 0; c < NC; c++) v[c] = zb[c * MF];
        float run = 0.f;
#pragma unroll
        for (int c = 0; c < NC; c++) {
            zb[c * MF] = run;
            run += v[c];
        }
    }
}

// ---------------------------------------------------------------------------
// Output kernel: K' from block-scaled half (one FMA per element, no MUFU).
// bufA : 64x132 fp32 (Q, later masked A)       = 8448 fl
// bufKh: 128x136 half (k' both chunks)         = 8704 fl-equiv
// bufB1: 128x72 fp32 (S halves / V)            = 9216 fl
// ---------------------------------------------------------------------------
#define PA 132
#define PKH 136   // halves
#define PB1 72
#define OFF_KH 8448
#define OFF_B1 (8448 + 8704)
#define OUT_DSMEM ((8448 + 8704 + 9216) * 4)

__global__ void __launch_bounds__(256, 2) out_kernel(const float* __restrict__ vin,
                                                     float* __restrict__ outp) {
    extern __shared__ float sm[];
    float* bufA = sm;
    __half* bufKh = (__half*)(sm + OFF_KH);
    float* bufB1 = sm + OFF_B1;
    __shared__ float den4[256];
    __shared__ float den[64];
    __shared__ float dinv[64];

    const int t = threadIdx.x, wid = t >> 5, lane = t & 31;
    const int g = lane >> 2, tq = lane & 3;
    const int wm = wid >> 2, wn = wid & 3;
    const int c = blockIdx.x, bh = blockIdx.y, hp = blockIdx.z;
    const int b = bh >> 3, h = bh & 7;
    const int n0 = c * CK;
    const int r0c = hp * 64;
    const int NT1 = hp ? 4 : 2;
    const int NJT = hp ? 16 : 8;
    const int kIters = hp ? 8 : 4;    // V staging float4 iters
    const int kkit = hp ? 8 : 4;      // K' staging uint4 iters (rows/16)

    const __half* qbase = g_qp + (size_t)(bh * NN + n0 + r0c) * MF;
    const __half* kphb = g_kph + (size_t)(bh * NN + n0) * MF;
    const __half* Sbase = g_S + (size_t)(bh * NC + c) * MF * DHd;
    const float* zg = g_z + (bh * NC + c) * MF;
    const float kmaxv = g_kmax[bh];
    const float sc0 = 0.0625f * __expf(g_mblk[bh * 32 + 2 * c] - kmaxv);
    const float sc1 = 0.0625f * __expf(g_mblk[bh * 32 + 2 * c + 1] - kmaxv);
    const float ccst = 6.25e-6f;   // 0.0625 * 1e-4

    // den partial: q . (z_prev + 1e-6), q read as half2
    {
        int i = t >> 2, qq = t & 3;
        float s = 0.f;
        const __half2* qr2 = (const __half2*)(qbase + (size_t)i * MF + qq * 64);
        const float* zr = zg + qq * 64;
#pragma unroll 8
        for (int mm = 0; mm < 32; mm++) {
            float2 qf = __half22float2(qr2[mm]);
            s += qf.x * (zr[2 * mm] + 1e-6f) + qf.y * (zr[2 * mm + 1] + 1e-6f);
        }
        den4[t] = s;
    }

    float accA[2][4][4];
#pragma unroll
    for (int i = 0; i < 2; i++)
#pragma unroll
        for (int j = 0; j < 4; j++)
#pragma unroll
            for (int s = 0; s < 4; s++) accA[i][j][s] = 0.f;
    float acc2[2][2][4];
#pragma unroll
    for (int i = 0; i < 2; i++)
#pragma unroll
        for (int j = 0; j < 2; j++)
#pragma unroll
            for (int s = 0; s < 4; s++) acc2[i][j][s] = 0.f;

#pragma unroll 1
    for (int hf = 0; hf < 2; hf++) {
        if (hf) __syncthreads();
        // Stage Q half hf -> bufA (64 x 128 fp32), source half (exact cvt)
#pragma unroll
        for (int it = 0; it < 4; it++) {
            int idx = it * 256 + t;
            int row = idx >> 4, c8 = idx & 15;
            uint4 u = *(const uint4*)(qbase + (size_t)row * MF + hf * 128 + c8 * 8);
            float2 f0 = __half22float2(*(__half2*)&u.x);
            float2 f1 = __half22float2(*(__half2*)&u.y);
            float2 f2 = __half22float2(*(__half2*)&u.z);
            float2 f3 = __half22float2(*(__half2*)&u.w);
            float* dst = bufA + row * PA + c8 * 8;
            *(float4*)dst = make_float4(f0.x, f0.y, f1.x, f1.y);
            *(float4*)(dst + 4) = make_float4(f2.x, f2.y, f3.x, f3.y);
        }
        // Stage K' both chunks of half hf -> bufKh: k' = e*scale + c (FMA)
        for (int it = 0; it < kkit; it++) {
            int idx = it * 256 + t;
            int row = idx >> 4, c8 = idx & 15;
            float ssel = (row < 64) ? sc0 : sc1;
            uint4 u = *(const uint4*)(kphb + (size_t)row * MF + hf * 128 + c8 * 8);
            float2 f0 = __half22float2(*(__half2*)&u.x);
            float2 f1 = __half22float2(*(__half2*)&u.y);
            float2 f2 = __half22float2(*(__half2*)&u.z);
            float2 f3 = __half22float2(*(__half2*)&u.w);
            __half2 h0 = __floats2half2_rn(fmaf(f0.x, ssel, ccst), fmaf(f0.y, ssel, ccst));
            __half2 h1 = __floats2half2_rn(fmaf(f1.x, ssel, ccst), fmaf(f1.y, ssel, ccst));
            __half2 h2 = __floats2half2_rn(fmaf(f2.x, ssel, ccst), fmaf(f2.y, ssel, ccst));
            __half2 h3 = __floats2half2_rn(fmaf(f3.x, ssel, ccst), fmaf(f3.y, ssel, ccst));
            uint4 o;
            o.x = *(uint32_t*)&h0; o.y = *(uint32_t*)&h1;
            o.z = *(uint32_t*)&h2; o.w = *(uint32_t*)&h3;
            *(uint4*)(bufKh + row * PKH + c8 * 8) = o;
        }
        // Stage S half hf -> bufB1 (half source, exact cvt to fp32)
#pragma unroll
        for (int it = 0; it < 4; it++) {
            int idx = it * 256 + t;
            int row = idx >> 3, c8 = idx & 7;
            uint4 u = *(const uint4*)(Sbase + (size_t)(hf * 128 + row) * DHd + c8 * 8);
            float2 f0 = __half22float2(*(__half2*)&u.x);
            float2 f1 = __half22float2(*(__half2*)&u.y);
            float2 f2 = __half22float2(*(__half2*)&u.z);
            float2 f3 = __half22float2(*(__half2*)&u.w);
            float* dst = bufB1 + row * PB1 + c8 * 8;
            *(float4*)dst = make_float4(f0.x, f0.y, f1.x, f1.y);
            *(float4*)(dst + 4) = make_float4(f2.x, f2.y, f3.x, f3.y);
        }
        __syncthreads();
        if (hf == 0 && t < 64)
            den[t] = den4[4 * t] + den4[4 * t + 1] + den4[4 * t + 2] + den4[4 * t + 3];

        // Phase 1a: A cols 0..63 x K' cols 0..63
#pragma unroll
        for (int ks = 0; ks < 8; ks++) {
            uint32_t af[2][4];
#pragma unroll
            for (int mt = 0; mt < 2; mt++) {
                const float* ap = bufA + (wm * 32 + mt * 16 + g) * PA + ks * 8 + tq;
                af[mt][0] = __float_as_uint(ap[0]);
                af[mt][1] = __float_as_uint(ap[8 * PA]);
                af[mt][2] = __float_as_uint(ap[4]);
                af[mt][3] = __float_as_uint(ap[8 * PA + 4]);
            }
#pragma unroll
            for (int nt = 0; nt < 4; nt++) {
                if (nt >= NT1) break;
                const __half* bp = bufKh + ((wn * NT1 + nt) * 8 + g) * PKH + ks * 8 + tq;
                uint32_t bf[2] = {__float_as_uint(__half2float(bp[0])),
                                  __float_as_uint(__half2float(bp[4]))};
                mma16n8k8(accA[0][nt], af[0], bf);
                mma16n8k8(accA[1][nt], af[1], bf);
            }
        }
        // Phase 2 (S half hf): K = 128 over bufA cols 0..127
#pragma unroll 2
        for (int ks = 0; ks < 16; ks++) {
            uint32_t af[2][4];
#pragma unroll
            for (int mt = 0; mt < 2; mt++) {
                const float* ap = bufA + (wm * 32 + mt * 16 + g) * PA + ks * 8 + tq;
                af[mt][0] = __float_as_uint(ap[0]);
                af[mt][1] = __float_as_uint(ap[8 * PA]);
                af[mt][2] = __float_as_uint(ap[4]);
                af[mt][3] = __float_as_uint(ap[8 * PA + 4]);
            }
#pragma unroll
            for (int nt = 0; nt < 2; nt++) {
                const float* bp = bufB1 + (ks * 8 + tq) * PB1 + (wn * 2 + nt) * 8 + g;
                uint32_t bf[2] = {__float_as_uint(bp[0]), __float_as_uint(bp[4 * PB1])};
                mma16n8k8(acc2[0][nt], af[0], bf);
                mma16n8k8(acc2[1][nt], af[1], bf);
            }
        }
        // Phase 1b: A cols 64..127 x K' cols 64..127 (no sync needed)
#pragma unroll
        for (int ks = 0; ks < 8; ks++) {
            uint32_t af[2][4];
#pragma unroll
            for (int mt = 0; mt < 2; mt++) {
                const float* ap = bufA + (wm * 32 + mt * 16 + g) * PA + 64 + ks * 8 + tq;
                af[mt][0] = __float_as_uint(ap[0]);
                af[mt][1] = __float_as_uint(ap[8 * PA]);
                af[mt][2] = __float_as_uint(ap[4]);
                af[mt][3] = __float_as_uint(ap[8 * PA + 4]);
            }
#pragma unroll
            for (int nt = 0; nt < 4; nt++) {
                if (nt >= NT1) break;
                const __half* bp = bufKh + ((wn * NT1 + nt) * 8 + g) * PKH + 64 + ks * 8 + tq;
                uint32_t bf[2] = {__float_as_uint(__half2float(bp[0])),
                                  __float_as_uint(__half2float(bp[4]))};
                mma16n8k8(accA[0][nt], af[0], bf);
                mma16n8k8(accA[1][nt], af[1], bf);
            }
        }
    }

    // ---- Mask tril + rowsum -> den ----
#pragma unroll
    for (int mt = 0; mt < 2; mt++) {
        int i0 = wm * 32 + mt * 16 + g;
        int lim0 = r0c + i0, lim1 = lim0 + 8;
        float rs0 = 0.f, rs1 = 0.f;
#pragma unroll
        for (int nt = 0; nt < 4; nt++) {
            if (nt >= NT1) break;
            int cb = (wn * NT1 + nt) * 8 + tq * 2;
            float v0 = (cb     <= lim0) ? accA[mt][nt][0] : 0.f;
            float v1 = (cb + 1 <= lim0) ? accA[mt][nt][1] : 0.f;
            float v2 = (cb     <= lim1) ? accA[mt][nt][2] : 0.f;
            float v3 = (cb + 1 <= lim1) ? accA[mt][nt][3] : 0.f;
            accA[mt][nt][0] = v0; accA[mt][nt][1] = v1;
            accA[mt][nt][2] = v2; accA[mt][nt][3] = v3;
            rs0 += v0 + v1;
            rs1 += v2 + v3;
        }
        rs0 += __shfl_xor_sync(0xffffffffu, rs0, 1);
        rs0 += __shfl_xor_sync(0xffffffffu, rs0, 2);
        rs1 += __shfl_xor_sync(0xffffffffu, rs1, 1);
        rs1 += __shfl_xor_sync(0xffffffffu, rs1, 2);
        if (tq == 0) {
            atomicAdd(&den[i0], rs0);
            atomicAdd(&den[i0 + 8], rs1);
        }
    }
    __syncthreads();

    // ---- dinv; masked A -> bufA; V -> bufB1 ----
    if (t < 64) dinv[t] = 1.0f / den[t];
#pragma unroll
    for (int mt = 0; mt < 2; mt++) {
        int i0 = wm * 32 + mt * 16 + g;
#pragma unroll
        for (int nt = 0; nt < 4; nt++) {
            if (nt >= NT1) break;
            int j = (wn * NT1 + nt) * 8 + tq * 2;
            *(float2*)(bufA + i0 * PA + j) =
                make_float2(tf32r(accA[mt][nt][0]), tf32r(accA[mt][nt][1]));
            *(float2*)(bufA + (i0 + 8) * PA + j) =
                make_float2(tf32r(accA[mt][nt][2]), tf32r(accA[mt][nt][3]));
        }
    }
    for (int it = 0; it < kIters; it++) {
        int idx = it * 256 + t;
        int row = idx >> 4, c4 = idx & 15;
        float4 v = *(const float4*)(vin + ((size_t)(b * NN + n0 + row)) * Dd
                                    + h * DHd + c4 * 4);
        *(float4*)(bufB1 + row * PB1 + c4 * 4) = tf32v4(v);
    }
    __syncthreads();

    // ---- Phase 3: out += tril(A) . V ----
#pragma unroll 2
    for (int ks = 0; ks < 16; ks++) {
        if (ks >= NJT) break;
        uint32_t af[2][4];
#pragma unroll
        for (int mt = 0; mt < 2; mt++) {
            const float* ap = bufA + (wm * 32 + mt * 16 + g) * PA + ks * 8 + tq;
            af[mt][0] = __float_as_uint(ap[0]);
            af[mt][1] = __float_as_uint(ap[8 * PA]);
            af[mt][2] = __float_as_uint(ap[4]);
            af[mt][3] = __float_as_uint(ap[8 * PA + 4]);
        }
#pragma unroll
        for (int nt = 0; nt < 2; nt++) {
            const float* bp = bufB1 + (ks * 8 + tq) * PB1 + (wn * 2 + nt) * 8 + g;
            uint32_t bf[2] = {__float_as_uint(bp[0]), __float_as_uint(bp[4 * PB1])};
            mma16n8k8(acc2[0][nt], af[0], bf);
            mma16n8k8(acc2[1][nt], af[1], bf);
        }
    }

    // ---- Epilogue ----
#pragma unroll
    for (int mt = 0; mt < 2; mt++) {
        int i0 = wm * 32 + mt * 16 + g;
        float d0 = dinv[i0], d1 = dinv[i0 + 8];
        float* op0 = outp + ((size_t)(b * NN + n0 + r0c + i0)) * Dd + h * DHd;
        float* op1 = op0 + (size_t)8 * Dd;
#pragma unroll
        for (int nt = 0; nt < 2; nt++) {
            int e = (wn * 2 + nt) * 8 + tq * 2;
            *(float2*)(op0 + e) = make_float2(acc2[mt][nt][0] * d0,
                                              acc2[mt][nt][1] * d0);
            *(float2*)(op1 + e) = make_float2(acc2[mt][nt][2] * d1,
                                              acc2[mt][nt][3] * d1);
        }
    }
}

// ---------------------------------------------------------------------------
extern "C" void kernel_launch(void* const* d_in, const int* in_sizes, int n_in,
                              void* d_out, int out_size) {
    (void)in_sizes; (void)n_in; (void)out_size;
    const float* q    = (const float*)d_in[0];
    const float* k    = (const float*)d_in[1];
    const float* v    = (const float*)d_in[2];
    const float* proj = (const float*)d_in[3];
    float* out = (float*)d_out;

    cudaFuncSetAttribute(out_kernel, cudaFuncAttributeMaxDynamicSharedMemorySize,
                         OUT_DSMEM);

    feat_kernel<true><<<dim3(32, 32), 256>>>(q, proj);
    feat_kernel<false><<<dim3(32, 32), 256>>>(k, proj);
    chunk_kv_kernel<<<dim3(16, 32), 256>>>(v);
    prefix_kernel<<<1056, 256>>>();
    out_kernel<<<dim3(16, 32, 2), 256, OUT_DSMEM>>>(v, out);
}

// round 15
// speedup vs baseline: 1.3905x; 1.1258x over previous
#include <cuda_runtime.h>
#include <cuda_fp16.h>
#include <math.h>
#include <stdint.h>

// Problem constants
#define Bb 4
#define Hh 8
#define BHn 32
#define NN 2048
#define Dd 512
#define DHd 64
#define MF 256
#define CK 128
#define NC 16

// Scratch
__device__ __align__(16) __half g_qp[(size_t)BHn * NN * MF];   // exp'd q feats (half)
__device__ __align__(16) __half g_kph[(size_t)BHn * NN * MF];  // exp(dd-diag-m_blk) (half)
__device__ __align__(16) __half g_S[(size_t)BHn * NC * MF * DHd]; // S (half)
__device__ float g_z [BHn * NC * MF];
__device__ float g_kmax[BHn];
__device__ float g_mblk[BHn * 32];   // per-64-row-block max of dd

__device__ __forceinline__ float tf32r(float x) {
    uint32_t u = __float_as_uint(x);
    u = (u + 0x1000u) & 0xFFFFE000u;
    return __uint_as_float(u);
}
__device__ __forceinline__ uint32_t tf32u(float x) {
    return (__float_as_uint(x) + 0x1000u) & 0xFFFFE000u;
}
__device__ __forceinline__ float4 tf32v4(float4 v) {
    v.x = tf32r(v.x); v.y = tf32r(v.y); v.z = tf32r(v.z); v.w = tf32r(v.w);
    return v;
}

// Warp-level tf32 MMA (portable ISA; tensor pipe)
__device__ __forceinline__ void mma16n8k8(float c[4], const uint32_t a[4],
                                          const uint32_t b[2]) {
    asm volatile(
        "mma.sync.aligned.m16n8k8.row.col.f32.tf32.tf32.f32 "
        "{%0,%1,%2,%3}, {%4,%5,%6,%7}, {%8,%9}, {%0,%1,%2,%3};"
        : "+f"(c[0]), "+f"(c[1]), "+f"(c[2]), "+f"(c[3])
        : "r"(a[0]), "r"(a[1]), "r"(a[2]), "r"(a[3]), "r"(b[0]), "r"(b[1]));
}

// ---------------------------------------------------------------------------
// Feature-map kernel: 2-mma split (x = ah + al exact; proj RN-rounded tf32).
// Q: exp'd half. K: block-scaled exp'd half + per-block max + global max.
// ---------------------------------------------------------------------------
template <bool IS_Q>
__global__ void __launch_bounds__(256) feat_kernel(const float* __restrict__ xin,
                                                   const float* __restrict__ proj) {
    __shared__ uint2 ps[2][1024];
    __shared__ float mx[64][2];
    __shared__ float bred[8];

    const int t = threadIdx.x, wid = t >> 5, lane = t & 31;
    const int g = lane >> 2, tq = lane & 3;
    const int wm = wid >> 1, wn = wid & 1;
    const int bh = blockIdx.y, b = bh >> 3, h = bh & 7;
    const int n0 = blockIdx.x * 64;
    const int r0 = n0 + wm * 16;

    if (IS_Q && blockIdx.x == 0 && t == 0) g_kmax[bh] = -1e30f;

    uint4 ah[8], al[8];
    float ss0 = 0.f, ss1 = 0.f;
    const float* xb = xin + ((size_t)b * NN + r0) * Dd + h * DHd;
#pragma unroll
    for (int ks = 0; ks < 8; ks++) {
        float x0 = xb[(size_t)g * Dd + ks * 8 + tq];
        float x1 = xb[(size_t)(g + 8) * Dd + ks * 8 + tq];
        float x2 = xb[(size_t)g * Dd + ks * 8 + tq + 4];
        float x3 = xb[(size_t)(g + 8) * Dd + ks * 8 + tq + 4];
        ss0 += x0 * x0 + x2 * x2;
        ss1 += x1 * x1 + x3 * x3;
        uint32_t h0 = __float_as_uint(x0) & 0xFFFFE000u;
        uint32_t h1 = __float_as_uint(x1) & 0xFFFFE000u;
        uint32_t h2 = __float_as_uint(x2) & 0xFFFFE000u;
        uint32_t h3 = __float_as_uint(x3) & 0xFFFFE000u;
        ah[ks] = make_uint4(h0, h1, h2, h3);
        al[ks] = make_uint4(__float_as_uint(x0 - __uint_as_float(h0)),
                            __float_as_uint(x1 - __uint_as_float(h1)),
                            __float_as_uint(x2 - __uint_as_float(h2)),
                            __float_as_uint(x3 - __uint_as_float(h3)));
    }
    ss0 += __shfl_xor_sync(0xffffffffu, ss0, 1);
    ss0 += __shfl_xor_sync(0xffffffffu, ss0, 2);
    ss1 += __shfl_xor_sync(0xffffffffu, ss1, 1);
    ss1 += __shfl_xor_sync(0xffffffffu, ss1, 2);
    const float diag0 = ss0 * 0.0625f, diag1 = ss1 * 0.0625f;

    float acc[16][4];
#pragma unroll
    for (int i = 0; i < 16; i++)
#pragma unroll
        for (int j = 0; j < 4; j++) acc[i][j] = 0.f;

    // Prologue: stage ks=0 into buffer 0 (proj RN-rounded tf32)
#pragma unroll
    for (int it = 0; it < 4; it++) {
        int slot = it * 256 + t;
        int nt = slot >> 5, sl = slot & 31;
        int sg = sl >> 2, stq = sl & 3;
        const float* pp = proj + (nt * 8 + sg) * 64 + stq;
        ps[0][slot] = make_uint2(tf32u(pp[0]), tf32u(pp[4]));
    }

    for (int ks = 0; ks < 8; ks++) {
        __syncthreads();
        if (ks < 7) {
            int sks = ks + 1, buf = sks & 1;
#pragma unroll
            for (int it = 0; it < 4; it++) {
                int slot = it * 256 + t;
                int nt = slot >> 5, sl = slot & 31;
                int sg = sl >> 2, stq = sl & 3;
                const float* pp = proj + (nt * 8 + sg) * 64 + sks * 8 + stq;
                ps[buf][slot] = make_uint2(tf32u(pp[0]), tf32u(pp[4]));
            }
        }
        const uint2* pb = ps[ks & 1];
#pragma unroll
        for (int ntl = 0; ntl < 16; ntl++) {
            uint2 pv = pb[(wn * 16 + ntl) * 32 + lane];
            uint32_t bf[2] = {pv.x, pv.y};
            mma16n8k8(acc[ntl], (const uint32_t*)&ah[ks], bf);
            mma16n8k8(acc[ntl], (const uint32_t*)&al[ks], bf);
        }
    }

    const float normalizer = 0.35355339059327373f;
#pragma unroll
    for (int ntl = 0; ntl < 16; ntl++)
#pragma unroll
        for (int j = 0; j < 4; j++) acc[ntl][j] *= normalizer;

    if (IS_Q) {
        float m0 = -1e30f, m1 = -1e30f;
#pragma unroll
        for (int ntl = 0; ntl < 16; ntl++) {
            m0 = fmaxf(m0, fmaxf(acc[ntl][0], acc[ntl][1]));
            m1 = fmaxf(m1, fmaxf(acc[ntl][2], acc[ntl][3]));
        }
        m0 = fmaxf(m0, __shfl_xor_sync(0xffffffffu, m0, 1));
        m0 = fmaxf(m0, __shfl_xor_sync(0xffffffffu, m0, 2));
        m1 = fmaxf(m1, __shfl_xor_sync(0xffffffffu, m1, 1));
        m1 = fmaxf(m1, __shfl_xor_sync(0xffffffffu, m1, 2));
        if (tq == 0) {
            mx[wm * 16 + g][wn] = m0;
            mx[wm * 16 + g + 8][wn] = m1;
        }
        __syncthreads();
        const float M0 = fmaxf(mx[wm * 16 + g][0], mx[wm * 16 + g][1]);
        const float M1 = fmaxf(mx[wm * 16 + g + 8][0], mx[wm * 16 + g + 8][1]);
        __half* o0 = g_qp + ((size_t)bh * NN + r0 + g) * MF + wn * 128;
        __half* o1 = g_qp + ((size_t)bh * NN + r0 + g + 8) * MF + wn * 128;
#pragma unroll
        for (int ntl = 0; ntl < 16; ntl++) {
            float a0 = 0.0625f * (__expf(acc[ntl][0] - diag0 - M0) + 1e-4f);
            float a1 = 0.0625f * (__expf(acc[ntl][1] - diag0 - M0) + 1e-4f);
            float a2 = 0.0625f * (__expf(acc[ntl][2] - diag1 - M1) + 1e-4f);
            float a3 = 0.0625f * (__expf(acc[ntl][3] - diag1 - M1) + 1e-4f);
            *(__half2*)(o0 + ntl * 8 + tq * 2) = __floats2half2_rn(a0, a1);
            *(__half2*)(o1 + ntl * 8 + tq * 2) = __floats2half2_rn(a2, a3);
        }
    } else {
        float km = -1e30f;
#pragma unroll
        for (int ntl = 0; ntl < 16; ntl++) {
            km = fmaxf(km, fmaxf(fmaxf(acc[ntl][0], acc[ntl][1]),
                                 fmaxf(acc[ntl][2], acc[ntl][3])));
        }
#pragma unroll
        for (int off = 16; off; off >>= 1)
            km = fmaxf(km, __shfl_xor_sync(0xffffffffu, km, off));
        if (lane == 0) bred[wid] = km;
        __syncthreads();
        float mblk = bred[0];
#pragma unroll
        for (int w = 1; w < 8; w++) mblk = fmaxf(mblk, bred[w]);

        __half* o0 = g_kph + ((size_t)bh * NN + r0 + g) * MF + wn * 128;
        __half* o1 = g_kph + ((size_t)bh * NN + r0 + g + 8) * MF + wn * 128;
#pragma unroll
        for (int ntl = 0; ntl < 16; ntl++) {
            float e0 = __expf(acc[ntl][0] - diag0 - mblk);
            float e1 = __expf(acc[ntl][1] - diag0 - mblk);
            float e2 = __expf(acc[ntl][2] - diag1 - mblk);
            float e3 = __expf(acc[ntl][3] - diag1 - mblk);
            *(__half2*)(o0 + ntl * 8 + tq * 2) = __floats2half2_rn(e0, e1);
            *(__half2*)(o1 + ntl * 8 + tq * 2) = __floats2half2_rn(e2, e3);
        }
        if (t == 0) {
            g_mblk[bh * 32 + blockIdx.x] = mblk;
            int* addr = (int*)&g_kmax[bh];
            int old = *addr;
            while (__int_as_float(old) < mblk) {
                int assumed = old;
                old = atomicCAS(addr, assumed, __float_as_int(mblk));
                if (old == assumed) break;
            }
        }
    }
}

// ---------------------------------------------------------------------------
// Per-chunk local KV state; k' from block-scaled half (no MUFU); S half out.
// ---------------------------------------------------------------------------
__global__ void __launch_bounds__(256) chunk_kv_kernel(const float* __restrict__ vin) {
    const int t = threadIdx.x, wid = t >> 5, lane = t & 31;
    const int g = lane >> 2, tq = lane & 3;
    const int c = blockIdx.x, bh = blockIdx.y;
    const int b = bh >> 3, h = bh & 7;
    const int n0 = c * CK;
    const __half* kb = g_kph + (size_t)(bh * NN + n0) * MF;
    const float* vb = vin + ((size_t)(b * NN + n0)) * Dd + h * DHd;
    const float m = g_kmax[bh];
    const float s0 = __expf(g_mblk[bh * 32 + 2 * c] - m);
    const float s1 = __expf(g_mblk[bh * 32 + 2 * c + 1] - m);

    float acc[2][8][4];
#pragma unroll
    for (int i = 0; i < 2; i++)
#pragma unroll
        for (int n = 0; n < 8; n++)
#pragma unroll
            for (int j = 0; j < 4; j++) acc[i][n][j] = 0.f;
    float z0[2] = {0.f, 0.f}, z1[2] = {0.f, 0.f};

    for (int tk = 0; tk < 16; tk++) {
        const int j0 = tk * 8 + tq, j1 = j0 + 4;
        const float sA = (tk < 8) ? s0 : s1;
        uint32_t af[2][4];
#pragma unroll
        for (int i = 0; i < 2; i++) {
            int mm = (wid * 2 + i) * 16 + g;
            float a0 = 0.0625f * (__half2float(kb[(size_t)j0 * MF + mm]) * sA + 1e-4f);
            float a1 = 0.0625f * (__half2float(kb[(size_t)j0 * MF + mm + 8]) * sA + 1e-4f);
            float a2 = 0.0625f * (__half2float(kb[(size_t)j1 * MF + mm]) * sA + 1e-4f);
            float a3 = 0.0625f * (__half2float(kb[(size_t)j1 * MF + mm + 8]) * sA + 1e-4f);
            z0[i] += a0 + a2;
            z1[i] += a1 + a3;
            af[i][0] = tf32u(a0); af[i][1] = tf32u(a1);
            af[i][2] = tf32u(a2); af[i][3] = tf32u(a3);
        }
#pragma unroll
        for (int nt = 0; nt < 8; nt++) {
            uint32_t bf[2];
            bf[0] = tf32u(vb[(size_t)j0 * Dd + nt * 8 + g]);
            bf[1] = tf32u(vb[(size_t)j1 * Dd + nt * 8 + g]);
            mma16n8k8(acc[0][nt], af[0], bf);
            mma16n8k8(acc[1][nt], af[1], bf);
        }
    }

#pragma unroll
    for (int i = 0; i < 2; i++) {
        z0[i] += __shfl_xor_sync(0xffffffffu, z0[i], 1);
        z0[i] += __shfl_xor_sync(0xffffffffu, z0[i], 2);
        z1[i] += __shfl_xor_sync(0xffffffffu, z1[i], 1);
        z1[i] += __shfl_xor_sync(0xffffffffu, z1[i], 2);
    }
    if (tq == 0) {
        float* zp = g_z + (bh * NC + c) * MF;
#pragma unroll
        for (int i = 0; i < 2; i++) {
            int mm = (wid * 2 + i) * 16 + g;
            zp[mm] = z0[i];
            zp[mm + 8] = z1[i];
        }
    }

    __half* Sp = g_S + (size_t)(bh * NC + c) * MF * DHd;
#pragma unroll
    for (int i = 0; i < 2; i++) {
        int mm = (wid * 2 + i) * 16 + g;
#pragma unroll
        for (int nt = 0; nt < 8; nt++) {
            *(__half2*)(Sp + (size_t)mm * DHd + nt * 8 + tq * 2) =
                __floats2half2_rn(acc[i][nt][0], acc[i][nt][1]);
            *(__half2*)(Sp + (size_t)(mm + 8) * DHd + nt * 8 + tq * 2) =
                __floats2half2_rn(acc[i][nt][2], acc[i][nt][3]);
        }
    }
}

// ---------------------------------------------------------------------------
// Fully parallel exclusive prefix (S as half2, fp32 carry; z fp32)
// ---------------------------------------------------------------------------
__global__ void __launch_bounds__(256) prefix_kernel() {
    const int blk = blockIdx.x;
    if (blk < 1024) {
        int idx = blk * 256 + threadIdx.x;
        int bh = idx >> 13;
        int me2 = idx & 8191;
        __half2* base = (__half2*)g_S + (size_t)bh * (NC * 8192) + me2;
        float2 v[NC];
#pragma unroll
        for (int c = 0; c < NC; c++) v[c] = __half22float2(base[(size_t)c * 8192]);
        float2 run = make_float2(0.f, 0.f);
#pragma unroll
        for (int c = 0; c < NC; c++) {
            base[(size_t)c * 8192] = __floats2half2_rn(run.x, run.y);
            run.x += v[c].x;
            run.y += v[c].y;
        }
    } else {
        int bh = blk - 1024;
        int mm = threadIdx.x;
        float* zb = g_z + bh * NC * MF + mm;
        float v[NC];
#pragma unroll
        for (int c = 0; c < NC; c++) v[c] = zb[c * MF];
        float run = 0.f;
#pragma unroll
        for (int c = 0; c < NC; c++) {
            zb[c * MF] = run;
            run += v[c];
        }
    }
}

// ---------------------------------------------------------------------------
// Output kernel (unchanged from round 14 winner).
// ---------------------------------------------------------------------------
#define PA 132
#define PKH 136   // halves
#define PB1 72
#define OFF_KH 8448
#define OFF_B1 (8448 + 8704)
#define OUT_DSMEM ((8448 + 8704 + 9216) * 4)

__global__ void __launch_bounds__(256, 2) out_kernel(const float* __restrict__ vin,
                                                     float* __restrict__ outp) {
    extern __shared__ float sm[];
    float* bufA = sm;
    __half* bufKh = (__half*)(sm + OFF_KH);
    float* bufB1 = sm + OFF_B1;
    __shared__ float den4[256];
    __shared__ float den[64];
    __shared__ float dinv[64];

    const int t = threadIdx.x, wid = t >> 5, lane = t & 31;
    const int g = lane >> 2, tq = lane & 3;
    const int wm = wid >> 2, wn = wid & 3;
    const int c = blockIdx.x, bh = blockIdx.y, hp = blockIdx.z;
    const int b = bh >> 3, h = bh & 7;
    const int n0 = c * CK;
    const int r0c = hp * 64;
    const int NT1 = hp ? 4 : 2;
    const int NJT = hp ? 16 : 8;
    const int kIters = hp ? 8 : 4;
    const int kkit = hp ? 8 : 4;

    const __half* qbase = g_qp + (size_t)(bh * NN + n0 + r0c) * MF;
    const __half* kphb = g_kph + (size_t)(bh * NN + n0) * MF;
    const __half* Sbase = g_S + (size_t)(bh * NC + c) * MF * DHd;
    const float* zg = g_z + (bh * NC + c) * MF;
    const float kmaxv = g_kmax[bh];
    const float sc0 = 0.0625f * __expf(g_mblk[bh * 32 + 2 * c] - kmaxv);
    const float sc1 = 0.0625f * __expf(g_mblk[bh * 32 + 2 * c + 1] - kmaxv);
    const float ccst = 6.25e-6f;

    {
        int i = t >> 2, qq = t & 3;
        float s = 0.f;
        const __half2* qr2 = (const __half2*)(qbase + (size_t)i * MF + qq * 64);
        const float* zr = zg + qq * 64;
#pragma unroll 8
        for (int mm = 0; mm < 32; mm++) {
            float2 qf = __half22float2(qr2[mm]);
            s += qf.x * (zr[2 * mm] + 1e-6f) + qf.y * (zr[2 * mm + 1] + 1e-6f);
        }
        den4[t] = s;
    }

    float accA[2][4][4];
#pragma unroll
    for (int i = 0; i < 2; i++)
#pragma unroll
        for (int j = 0; j < 4; j++)
#pragma unroll
            for (int s = 0; s < 4; s++) accA[i][j][s] = 0.f;
    float acc2[2][2][4];
#pragma unroll
    for (int i = 0; i < 2; i++)
#pragma unroll
        for (int j = 0; j < 2; j++)
#pragma unroll
            for (int s = 0; s < 4; s++) acc2[i][j][s] = 0.f;

#pragma unroll 1
    for (int hf = 0; hf < 2; hf++) {
        if (hf) __syncthreads();
#pragma unroll
        for (int it = 0; it < 4; it++) {
            int idx = it * 256 + t;
            int row = idx >> 4, c8 = idx & 15;
            uint4 u = *(const uint4*)(qbase + (size_t)row * MF + hf * 128 + c8 * 8);
            float2 f0 = __half22float2(*(__half2*)&u.x);
            float2 f1 = __half22float2(*(__half2*)&u.y);
            float2 f2 = __half22float2(*(__half2*)&u.z);
            float2 f3 = __half22float2(*(__half2*)&u.w);
            float* dst = bufA + row * PA + c8 * 8;
            *(float4*)dst = make_float4(f0.x, f0.y, f1.x, f1.y);
            *(float4*)(dst + 4) = make_float4(f2.x, f2.y, f3.x, f3.y);
        }
        for (int it = 0; it < kkit; it++) {
            int idx = it * 256 + t;
            int row = idx >> 4, c8 = idx & 15;
            float ssel = (row < 64) ? sc0 : sc1;
            uint4 u = *(const uint4*)(kphb + (size_t)row * MF + hf * 128 + c8 * 8);
            float2 f0 = __half22float2(*(__half2*)&u.x);
            float2 f1 = __half22float2(*(__half2*)&u.y);
            float2 f2 = __half22float2(*(__half2*)&u.z);
            float2 f3 = __half22float2(*(__half2*)&u.w);
            __half2 h0 = __floats2half2_rn(fmaf(f0.x, ssel, ccst), fmaf(f0.y, ssel, ccst));
            __half2 h1 = __floats2half2_rn(fmaf(f1.x, ssel, ccst), fmaf(f1.y, ssel, ccst));
            __half2 h2 = __floats2half2_rn(fmaf(f2.x, ssel, ccst), fmaf(f2.y, ssel, ccst));
            __half2 h3 = __floats2half2_rn(fmaf(f3.x, ssel, ccst), fmaf(f3.y, ssel, ccst));
            uint4 o;
            o.x = *(uint32_t*)&h0; o.y = *(uint32_t*)&h1;
            o.z = *(uint32_t*)&h2; o.w = *(uint32_t*)&h3;
            *(uint4*)(bufKh + row * PKH + c8 * 8) = o;
        }
#pragma unroll
        for (int it = 0; it < 4; it++) {
            int idx = it * 256 + t;
            int row = idx >> 3, c8 = idx & 7;
            uint4 u = *(const uint4*)(Sbase + (size_t)(hf * 128 + row) * DHd + c8 * 8);
            float2 f0 = __half22float2(*(__half2*)&u.x);
            float2 f1 = __half22float2(*(__half2*)&u.y);
            float2 f2 = __half22float2(*(__half2*)&u.z);
            float2 f3 = __half22float2(*(__half2*)&u.w);
            float* dst = bufB1 + row * PB1 + c8 * 8;
            *(float4*)dst = make_float4(f0.x, f0.y, f1.x, f1.y);
            *(float4*)(dst + 4) = make_float4(f2.x, f2.y, f3.x, f3.y);
        }
        __syncthreads();
        if (hf == 0 && t < 64)
            den[t] = den4[4 * t] + den4[4 * t + 1] + den4[4 * t + 2] + den4[4 * t + 3];

#pragma unroll
        for (int ks = 0; ks < 8; ks++) {
            uint32_t af[2][4];
#pragma unroll
            for (int mt = 0; mt < 2; mt++) {
                const float* ap = bufA + (wm * 32 + mt * 16 + g) * PA + ks * 8 + tq;
                af[mt][0] = __float_as_uint(ap[0]);
                af[mt][1] = __float_as_uint(ap[8 * PA]);
                af[mt][2] = __float_as_uint(ap[4]);
                af[mt][3] = __float_as_uint(ap[8 * PA + 4]);
            }
#pragma unroll
            for (int nt = 0; nt < 4; nt++) {
                if (nt >= NT1) break;
                const __half* bp = bufKh + ((wn * NT1 + nt) * 8 + g) * PKH + ks * 8 + tq;
                uint32_t bf[2] = {__float_as_uint(__half2float(bp[0])),
                                  __float_as_uint(__half2float(bp[4]))};
                mma16n8k8(accA[0][nt], af[0], bf);
                mma16n8k8(accA[1][nt], af[1], bf);
            }
        }
#pragma unroll 2
        for (int ks = 0; ks < 16; ks++) {
            uint32_t af[2][4];
#pragma unroll
            for (int mt = 0; mt < 2; mt++) {
                const float* ap = bufA + (wm * 32 + mt * 16 + g) * PA + ks * 8 + tq;
                af[mt][0] = __float_as_uint(ap[0]);
                af[mt][1] = __float_as_uint(ap[8 * PA]);
                af[mt][2] = __float_as_uint(ap[4]);
                af[mt][3] = __float_as_uint(ap[8 * PA + 4]);
            }
#pragma unroll
            for (int nt = 0; nt < 2; nt++) {
                const float* bp = bufB1 + (ks * 8 + tq) * PB1 + (wn * 2 + nt) * 8 + g;
                uint32_t bf[2] = {__float_as_uint(bp[0]), __float_as_uint(bp[4 * PB1])};
                mma16n8k8(acc2[0][nt], af[0], bf);
                mma16n8k8(acc2[1][nt], af[1], bf);
            }
        }
#pragma unroll
        for (int ks = 0; ks < 8; ks++) {
            uint32_t af[2][4];
#pragma unroll
            for (int mt = 0; mt < 2; mt++) {
                const float* ap = bufA + (wm * 32 + mt * 16 + g) * PA + 64 + ks * 8 + tq;
                af[mt][0] = __float_as_uint(ap[0]);
                af[mt][1] = __float_as_uint(ap[8 * PA]);
                af[mt][2] = __float_as_uint(ap[4]);
                af[mt][3] = __float_as_uint(ap[8 * PA + 4]);
            }
#pragma unroll
            for (int nt = 0; nt < 4; nt++) {
                if (nt >= NT1) break;
                const __half* bp = bufKh + ((wn * NT1 + nt) * 8 + g) * PKH + 64 + ks * 8 + tq;
                uint32_t bf[2] = {__float_as_uint(__half2float(bp[0])),
                                  __float_as_uint(__half2float(bp[4]))};
                mma16n8k8(accA[0][nt], af[0], bf);
                mma16n8k8(accA[1][nt], af[1], bf);
            }
        }
    }

#pragma unroll
    for (int mt = 0; mt < 2; mt++) {
        int i0 = wm * 32 + mt * 16 + g;
        int lim0 = r0c + i0, lim1 = lim0 + 8;
        float rs0 = 0.f, rs1 = 0.f;
#pragma unroll
        for (int nt = 0; nt < 4; nt++) {
            if (nt >= NT1) break;
            int cb = (wn * NT1 + nt) * 8 + tq * 2;
            float v0 = (cb     <= lim0) ? accA[mt][nt][0] : 0.f;
            float v1 = (cb + 1 <= lim0) ? accA[mt][nt][1] : 0.f;
            float v2 = (cb     <= lim1) ? accA[mt][nt][2] : 0.f;
            float v3 = (cb + 1 <= lim1) ? accA[mt][nt][3] : 0.f;
            accA[mt][nt][0] = v0; accA[mt][nt][1] = v1;
            accA[mt][nt][2] = v2; accA[mt][nt][3] = v3;
            rs0 += v0 + v1;
            rs1 += v2 + v3;
        }
        rs0 += __shfl_xor_sync(0xffffffffu, rs0, 1);
        rs0 += __shfl_xor_sync(0xffffffffu, rs0, 2);
        rs1 += __shfl_xor_sync(0xffffffffu, rs1, 1);
        rs1 += __shfl_xor_sync(0xffffffffu, rs1, 2);
        if (tq == 0) {
            atomicAdd(&den[i0], rs0);
            atomicAdd(&den[i0 + 8], rs1);
        }
    }
    __syncthreads();

    if (t < 64) dinv[t] = 1.0f / den[t];
#pragma unroll
    for (int mt = 0; mt < 2; mt++) {
        int i0 = wm * 32 + mt * 16 + g;
#pragma unroll
        for (int nt = 0; nt < 4; nt++) {
            if (nt >= NT1) break;
            int j = (wn * NT1 + nt) * 8 + tq * 2;
            *(float2*)(bufA + i0 * PA + j) =
                make_float2(tf32r(accA[mt][nt][0]), tf32r(accA[mt][nt][1]));
            *(float2*)(bufA + (i0 + 8) * PA + j) =
                make_float2(tf32r(accA[mt][nt][2]), tf32r(accA[mt][nt][3]));
        }
    }
    for (int it = 0; it < kIters; it++) {
        int idx = it * 256 + t;
        int row = idx >> 4, c4 = idx & 15;
        float4 v = *(const float4*)(vin + ((size_t)(b * NN + n0 + row)) * Dd
                                    + h * DHd + c4 * 4);
        *(float4*)(bufB1 + row * PB1 + c4 * 4) = tf32v4(v);
    }
    __syncthreads();

#pragma unroll 2
    for (int ks = 0; ks < 16; ks++) {
        if (ks >= NJT) break;
        uint32_t af[2][4];
#pragma unroll
        for (int mt = 0; mt < 2; mt++) {
            const float* ap = bufA + (wm * 32 + mt * 16 + g) * PA + ks * 8 + tq;
            af[mt][0] = __float_as_uint(ap[0]);
            af[mt][1] = __float_as_uint(ap[8 * PA]);
            af[mt][2] = __float_as_uint(ap[4]);
            af[mt][3] = __float_as_uint(ap[8 * PA + 4]);
        }
#pragma unroll
        for (int nt = 0; nt < 2; nt++) {
            const float* bp = bufB1 + (ks * 8 + tq) * PB1 + (wn * 2 + nt) * 8 + g;
            uint32_t bf[2] = {__float_as_uint(bp[0]), __float_as_uint(bp[4 * PB1])};
            mma16n8k8(acc2[0][nt], af[0], bf);
            mma16n8k8(acc2[1][nt], af[1], bf);
        }
    }

#pragma unroll
    for (int mt = 0; mt < 2; mt++) {
        int i0 = wm * 32 + mt * 16 + g;
        float d0 = dinv[i0], d1 = dinv[i0 + 8];
        float* op0 = outp + ((size_t)(b * NN + n0 + r0c + i0)) * Dd + h * DHd;
        float* op1 = op0 + (size_t)8 * Dd;
#pragma unroll
        for (int nt = 0; nt < 2; nt++) {
            int e = (wn * 2 + nt) * 8 + tq * 2;
            *(float2*)(op0 + e) = make_float2(acc2[mt][nt][0] * d0,
                                              acc2[mt][nt][1] * d0);
            *(float2*)(op1 + e) = make_float2(acc2[mt][nt][2] * d1,
                                              acc2[mt][nt][3] * d1);
        }
    }
}

// ---------------------------------------------------------------------------
extern "C" void kernel_launch(void* const* d_in, const int* in_sizes, int n_in,
                              void* d_out, int out_size) {
    (void)in_sizes; (void)n_in; (void)out_size;
    const float* q    = (const float*)d_in[0];
    const float* k    = (const float*)d_in[1];
    const float* v    = (const float*)d_in[2];
    const float* proj = (const float*)d_in[3];
    float* out = (float*)d_out;

    cudaFuncSetAttribute(out_kernel, cudaFuncAttributeMaxDynamicSharedMemorySize,
                         OUT_DSMEM);

    feat_kernel<true><<<dim3(32, 32), 256>>>(q, proj);
    feat_kernel<false><<<dim3(32, 32), 256>>>(k, proj);
    chunk_kv_kernel<<<dim3(16, 32), 256>>>(v);
    prefix_kernel<<<1056, 256>>>();
    out_kernel<<<dim3(16, 32, 2), 256, OUT_DSMEM>>>(v, out);
}

// round 17
// speedup vs baseline: 1.4396x; 1.0353x over previous
#include <cuda_runtime.h>
#include <cuda_fp16.h>
#include <math.h>
#include <stdint.h>

// Problem constants
#define Bb 4
#define Hh 8
#define BHn 32
#define NN 2048
#define Dd 512
#define DHd 64
#define MF 256
#define CK 128
#define NC 16

// Scratch
__device__ __align__(16) __half g_qp[(size_t)BHn * NN * MF];   // exp'd q feats (half)
__device__ __align__(16) __half g_kph[(size_t)BHn * NN * MF];  // exp(dd-diag-m_blk) (half)
__device__ __align__(16) __half g_S[(size_t)BHn * NC * MF * DHd]; // S (half)
__device__ float g_z [BHn * NC * MF];
__device__ float g_kmax[BHn];
__device__ float g_mblk[BHn * 32];   // per-64-row-block max of dd

__device__ __forceinline__ float tf32r(float x) {
    uint32_t u = __float_as_uint(x);
    u = (u + 0x1000u) & 0xFFFFE000u;
    return __uint_as_float(u);
}
__device__ __forceinline__ uint32_t tf32u(float x) {
    return (__float_as_uint(x) + 0x1000u) & 0xFFFFE000u;
}
__device__ __forceinline__ float4 tf32v4(float4 v) {
    v.x = tf32r(v.x); v.y = tf32r(v.y); v.z = tf32r(v.z); v.w = tf32r(v.w);
    return v;
}

// Warp-level tf32 MMA (portable ISA; tensor pipe)
__device__ __forceinline__ void mma16n8k8(float c[4], const uint32_t a[4],
                                          const uint32_t b[2]) {
    asm volatile(
        "mma.sync.aligned.m16n8k8.row.col.f32.tf32.tf32.f32 "
        "{%0,%1,%2,%3}, {%4,%5,%6,%7}, {%8,%9}, {%0,%1,%2,%3};"
        : "+f"(c[0]), "+f"(c[1]), "+f"(c[2]), "+f"(c[3])
        : "r"(a[0]), "r"(a[1]), "r"(a[2]), "r"(a[3]), "r"(b[0]), "r"(b[1]));
}

// ---------------------------------------------------------------------------
// Feature-map kernel: single RN-tf32 MMA (x and proj both RN tf32).
// Measured-calibrated: p-side RN added only ~0.8e-4 rel_err; x-side is the
// same noise class. Q: exp'd half. K: block-scaled exp'd half + maxes.
// ---------------------------------------------------------------------------
template <bool IS_Q>
__global__ void __launch_bounds__(256) feat_kernel(const float* __restrict__ xin,
                                                   const float* __restrict__ proj) {
    __shared__ uint2 ps[2][1024];
    __shared__ float mx[64][2];
    __shared__ float bred[8];

    const int t = threadIdx.x, wid = t >> 5, lane = t & 31;
    const int g = lane >> 2, tq = lane & 3;
    const int wm = wid >> 1, wn = wid & 1;
    const int bh = blockIdx.y, b = bh >> 3, h = bh & 7;
    const int n0 = blockIdx.x * 64;
    const int r0 = n0 + wm * 16;

    if (IS_Q && blockIdx.x == 0 && t == 0) g_kmax[bh] = -1e30f;

    uint4 ah[8];
    float ss0 = 0.f, ss1 = 0.f;
    const float* xb = xin + ((size_t)b * NN + r0) * Dd + h * DHd;
#pragma unroll
    for (int ks = 0; ks < 8; ks++) {
        float x0 = xb[(size_t)g * Dd + ks * 8 + tq];
        float x1 = xb[(size_t)(g + 8) * Dd + ks * 8 + tq];
        float x2 = xb[(size_t)g * Dd + ks * 8 + tq + 4];
        float x3 = xb[(size_t)(g + 8) * Dd + ks * 8 + tq + 4];
        ss0 += x0 * x0 + x2 * x2;
        ss1 += x1 * x1 + x3 * x3;
        ah[ks] = make_uint4(tf32u(x0), tf32u(x1), tf32u(x2), tf32u(x3));
    }
    ss0 += __shfl_xor_sync(0xffffffffu, ss0, 1);
    ss0 += __shfl_xor_sync(0xffffffffu, ss0, 2);
    ss1 += __shfl_xor_sync(0xffffffffu, ss1, 1);
    ss1 += __shfl_xor_sync(0xffffffffu, ss1, 2);
    const float diag0 = ss0 * 0.0625f, diag1 = ss1 * 0.0625f;

    float acc[16][4];
#pragma unroll
    for (int i = 0; i < 16; i++)
#pragma unroll
        for (int j = 0; j < 4; j++) acc[i][j] = 0.f;

    // Prologue: stage ks=0 into buffer 0 (proj RN tf32)
#pragma unroll
    for (int it = 0; it < 4; it++) {
        int slot = it * 256 + t;
        int nt = slot >> 5, sl = slot & 31;
        int sg = sl >> 2, stq = sl & 3;
        const float* pp = proj + (nt * 8 + sg) * 64 + stq;
        ps[0][slot] = make_uint2(tf32u(pp[0]), tf32u(pp[4]));
    }

    for (int ks = 0; ks < 8; ks++) {
        __syncthreads();
        if (ks < 7) {
            int sks = ks + 1, buf = sks & 1;
#pragma unroll
            for (int it = 0; it < 4; it++) {
                int slot = it * 256 + t;
                int nt = slot >> 5, sl = slot & 31;
                int sg = sl >> 2, stq = sl & 3;
                const float* pp = proj + (nt * 8 + sg) * 64 + sks * 8 + stq;
                ps[buf][slot] = make_uint2(tf32u(pp[0]), tf32u(pp[4]));
            }
        }
        const uint2* pb = ps[ks & 1];
#pragma unroll
        for (int ntl = 0; ntl < 16; ntl++) {
            uint2 pv = pb[(wn * 16 + ntl) * 32 + lane];
            uint32_t bf[2] = {pv.x, pv.y};
            mma16n8k8(acc[ntl], (const uint32_t*)&ah[ks], bf);
        }
    }

    const float normalizer = 0.35355339059327373f;
#pragma unroll
    for (int ntl = 0; ntl < 16; ntl++)
#pragma unroll
        for (int j = 0; j < 4; j++) acc[ntl][j] *= normalizer;

    if (IS_Q) {
        float m0 = -1e30f, m1 = -1e30f;
#pragma unroll
        for (int ntl = 0; ntl < 16; ntl++) {
            m0 = fmaxf(m0, fmaxf(acc[ntl][0], acc[ntl][1]));
            m1 = fmaxf(m1, fmaxf(acc[ntl][2], acc[ntl][3]));
        }
        m0 = fmaxf(m0, __shfl_xor_sync(0xffffffffu, m0, 1));
        m0 = fmaxf(m0, __shfl_xor_sync(0xffffffffu, m0, 2));
        m1 = fmaxf(m1, __shfl_xor_sync(0xffffffffu, m1, 1));
        m1 = fmaxf(m1, __shfl_xor_sync(0xffffffffu, m1, 2));
        if (tq == 0) {
            mx[wm * 16 + g][wn] = m0;
            mx[wm * 16 + g + 8][wn] = m1;
        }
        __syncthreads();
        const float M0 = fmaxf(mx[wm * 16 + g][0], mx[wm * 16 + g][1]);
        const float M1 = fmaxf(mx[wm * 16 + g + 8][0], mx[wm * 16 + g + 8][1]);
        __half* o0 = g_qp + ((size_t)bh * NN + r0 + g) * MF + wn * 128;
        __half* o1 = g_qp + ((size_t)bh * NN + r0 + g + 8) * MF + wn * 128;
#pragma unroll
        for (int ntl = 0; ntl < 16; ntl++) {
            float a0 = 0.0625f * (__expf(acc[ntl][0] - diag0 - M0) + 1e-4f);
            float a1 = 0.0625f * (__expf(acc[ntl][1] - diag0 - M0) + 1e-4f);
            float a2 = 0.0625f * (__expf(acc[ntl][2] - diag1 - M1) + 1e-4f);
            float a3 = 0.0625f * (__expf(acc[ntl][3] - diag1 - M1) + 1e-4f);
            *(__half2*)(o0 + ntl * 8 + tq * 2) = __floats2half2_rn(a0, a1);
            *(__half2*)(o1 + ntl * 8 + tq * 2) = __floats2half2_rn(a2, a3);
        }
    } else {
        float km = -1e30f;
#pragma unroll
        for (int ntl = 0; ntl < 16; ntl++) {
            km = fmaxf(km, fmaxf(fmaxf(acc[ntl][0], acc[ntl][1]),
                                 fmaxf(acc[ntl][2], acc[ntl][3])));
        }
#pragma unroll
        for (int off = 16; off; off >>= 1)
            km = fmaxf(km, __shfl_xor_sync(0xffffffffu, km, off));
        if (lane == 0) bred[wid] = km;
        __syncthreads();
        float mblk = bred[0];
#pragma unroll
        for (int w = 1; w < 8; w++) mblk = fmaxf(mblk, bred[w]);

        __half* o0 = g_kph + ((size_t)bh * NN + r0 + g) * MF + wn * 128;
        __half* o1 = g_kph + ((size_t)bh * NN + r0 + g + 8) * MF + wn * 128;
#pragma unroll
        for (int ntl = 0; ntl < 16; ntl++) {
            float e0 = __expf(acc[ntl][0] - diag0 - mblk);
            float e1 = __expf(acc[ntl][1] - diag0 - mblk);
            float e2 = __expf(acc[ntl][2] - diag1 - mblk);
            float e3 = __expf(acc[ntl][3] - diag1 - mblk);
            *(__half2*)(o0 + ntl * 8 + tq * 2) = __floats2half2_rn(e0, e1);
            *(__half2*)(o1 + ntl * 8 + tq * 2) = __floats2half2_rn(e2, e3);
        }
        if (t == 0) {
            g_mblk[bh * 32 + blockIdx.x] = mblk;
            int* addr = (int*)&g_kmax[bh];
            int old = *addr;
            while (__int_as_float(old) < mblk) {
                int assumed = old;
                old = atomicCAS(addr, assumed, __float_as_int(mblk));
                if (old == assumed) break;
            }
        }
    }
}

// ---------------------------------------------------------------------------
// Per-chunk local KV state (unchanged from round 15)
// ---------------------------------------------------------------------------
__global__ void __launch_bounds__(256) chunk_kv_kernel(const float* __restrict__ vin) {
    const int t = threadIdx.x, wid = t >> 5, lane = t & 31;
    const int g = lane >> 2, tq = lane & 3;
    const int c = blockIdx.x, bh = blockIdx.y;
    const int b = bh >> 3, h = bh & 7;
    const int n0 = c * CK;
    const __half* kb = g_kph + (size_t)(bh * NN + n0) * MF;
    const float* vb = vin + ((size_t)(b * NN + n0)) * Dd + h * DHd;
    const float m = g_kmax[bh];
    const float s0 = __expf(g_mblk[bh * 32 + 2 * c] - m);
    const float s1 = __expf(g_mblk[bh * 32 + 2 * c + 1] - m);

    float acc[2][8][4];
#pragma unroll
    for (int i = 0; i < 2; i++)
#pragma unroll
        for (int n = 0; n < 8; n++)
#pragma unroll
            for (int j = 0; j < 4; j++) acc[i][n][j] = 0.f;
    float z0[2] = {0.f, 0.f}, z1[2] = {0.f, 0.f};

    for (int tk = 0; tk < 16; tk++) {
        const int j0 = tk * 8 + tq, j1 = j0 + 4;
        const float sA = (tk < 8) ? s0 : s1;
        uint32_t af[2][4];
#pragma unroll
        for (int i = 0; i < 2; i++) {
            int mm = (wid * 2 + i) * 16 + g;
            float a0 = 0.0625f * (__half2float(kb[(size_t)j0 * MF + mm]) * sA + 1e-4f);
            float a1 = 0.0625f * (__half2float(kb[(size_t)j0 * MF + mm + 8]) * sA + 1e-4f);
            float a2 = 0.0625f * (__half2float(kb[(size_t)j1 * MF + mm]) * sA + 1e-4f);
            float a3 = 0.0625f * (__half2float(kb[(size_t)j1 * MF + mm + 8]) * sA + 1e-4f);
            z0[i] += a0 + a2;
            z1[i] += a1 + a3;
            af[i][0] = tf32u(a0); af[i][1] = tf32u(a1);
            af[i][2] = tf32u(a2); af[i][3] = tf32u(a3);
        }
#pragma unroll
        for (int nt = 0; nt < 8; nt++) {
            uint32_t bf[2];
            bf[0] = tf32u(vb[(size_t)j0 * Dd + nt * 8 + g]);
            bf[1] = tf32u(vb[(size_t)j1 * Dd + nt * 8 + g]);
            mma16n8k8(acc[0][nt], af[0], bf);
            mma16n8k8(acc[1][nt], af[1], bf);
        }
    }

#pragma unroll
    for (int i = 0; i < 2; i++) {
        z0[i] += __shfl_xor_sync(0xffffffffu, z0[i], 1);
        z0[i] += __shfl_xor_sync(0xffffffffu, z0[i], 2);
        z1[i] += __shfl_xor_sync(0xffffffffu, z1[i], 1);
        z1[i] += __shfl_xor_sync(0xffffffffu, z1[i], 2);
    }
    if (tq == 0) {
        float* zp = g_z + (bh * NC + c) * MF;
#pragma unroll
        for (int i = 0; i < 2; i++) {
            int mm = (wid * 2 + i) * 16 + g;
            zp[mm] = z0[i];
            zp[mm + 8] = z1[i];
        }
    }

    __half* Sp = g_S + (size_t)(bh * NC + c) * MF * DHd;
#pragma unroll
    for (int i = 0; i < 2; i++) {
        int mm = (wid * 2 + i) * 16 + g;
#pragma unroll
        for (int nt = 0; nt < 8; nt++) {
            *(__half2*)(Sp + (size_t)mm * DHd + nt * 8 + tq * 2) =
                __floats2half2_rn(acc[i][nt][0], acc[i][nt][1]);
            *(__half2*)(Sp + (size_t)(mm + 8) * DHd + nt * 8 + tq * 2) =
                __floats2half2_rn(acc[i][nt][2], acc[i][nt][3]);
        }
    }
}

// ---------------------------------------------------------------------------
// Fully parallel exclusive prefix (unchanged)
// ---------------------------------------------------------------------------
__global__ void __launch_bounds__(256) prefix_kernel() {
    const int blk = blockIdx.x;
    if (blk < 1024) {
        int idx = blk * 256 + threadIdx.x;
        int bh = idx >> 13;
        int me2 = idx & 8191;
        __half2* base = (__half2*)g_S + (size_t)bh * (NC * 8192) + me2;
        float2 v[NC];
#pragma unroll
        for (int c = 0; c < NC; c++) v[c] = __half22float2(base[(size_t)c * 8192]);
        float2 run = make_float2(0.f, 0.f);
#pragma unroll
        for (int c = 0; c < NC; c++) {
            base[(size_t)c * 8192] = __floats2half2_rn(run.x, run.y);
            run.x += v[c].x;
            run.y += v[c].y;
        }
    } else {
        int bh = blk - 1024;
        int mm = threadIdx.x;
        float* zb = g_z + bh * NC * MF + mm;
        float v[NC];
#pragma unroll
        for (int c = 0; c < NC; c++) v[c] = zb[c * MF];
        float run = 0.f;
#pragma unroll
        for (int c = 0; c < NC; c++) {
            zb[c * MF] = run;
            run += v[c];
        }
    }
}

// ---------------------------------------------------------------------------
// Output kernel (round-15 version exactly — proven 240.1us).
// ---------------------------------------------------------------------------
#define PA 132
#define PKH 136   // halves
#define PB1 72
#define OFF_KH 8448
#define OFF_B1 (8448 + 8704)
#define OUT_DSMEM ((8448 + 8704 + 9216) * 4)

__global__ void __launch_bounds__(256, 2) out_kernel(const float* __restrict__ vin,
                                                     float* __restrict__ outp) {
    extern __shared__ float sm[];
    float* bufA = sm;
    __half* bufKh = (__half*)(sm + OFF_KH);
    float* bufB1 = sm + OFF_B1;
    __shared__ float den4[256];
    __shared__ float den[64];
    __shared__ float dinv[64];

    const int t = threadIdx.x, wid = t >> 5, lane = t & 31;
    const int g = lane >> 2, tq = lane & 3;
    const int wm = wid >> 2, wn = wid & 3;
    const int c = blockIdx.x, bh = blockIdx.y, hp = blockIdx.z;
    const int b = bh >> 3, h = bh & 7;
    const int n0 = c * CK;
    const int r0c = hp * 64;
    const int NT1 = hp ? 4 : 2;
    const int NJT = hp ? 16 : 8;
    const int kIters = hp ? 8 : 4;
    const int kkit = hp ? 8 : 4;

    const __half* qbase = g_qp + (size_t)(bh * NN + n0 + r0c) * MF;
    const __half* kphb = g_kph + (size_t)(bh * NN + n0) * MF;
    const __half* Sbase = g_S + (size_t)(bh * NC + c) * MF * DHd;
    const float* zg = g_z + (bh * NC + c) * MF;
    const float kmaxv = g_kmax[bh];
    const float sc0 = 0.0625f * __expf(g_mblk[bh * 32 + 2 * c] - kmaxv);
    const float sc1 = 0.0625f * __expf(g_mblk[bh * 32 + 2 * c + 1] - kmaxv);
    const float ccst = 6.25e-6f;

    {
        int i = t >> 2, qq = t & 3;
        float s = 0.f;
        const __half2* qr2 = (const __half2*)(qbase + (size_t)i * MF + qq * 64);
        const float* zr = zg + qq * 64;
#pragma unroll 8
        for (int mm = 0; mm < 32; mm++) {
            float2 qf = __half22float2(qr2[mm]);
            s += qf.x * (zr[2 * mm] + 1e-6f) + qf.y * (zr[2 * mm + 1] + 1e-6f);
        }
        den4[t] = s;
    }

    float accA[2][4][4];
#pragma unroll
    for (int i = 0; i < 2; i++)
#pragma unroll
        for (int j = 0; j < 4; j++)
#pragma unroll
            for (int s = 0; s < 4; s++) accA[i][j][s] = 0.f;
    float acc2[2][2][4];
#pragma unroll
    for (int i = 0; i < 2; i++)
#pragma unroll
        for (int j = 0; j < 2; j++)
#pragma unroll
            for (int s = 0; s < 4; s++) acc2[i][j][s] = 0.f;

#pragma unroll 1
    for (int hf = 0; hf < 2; hf++) {
        if (hf) __syncthreads();
#pragma unroll
        for (int it = 0; it < 4; it++) {
            int idx = it * 256 + t;
            int row = idx >> 4, c8 = idx & 15;
            uint4 u = *(const uint4*)(qbase + (size_t)row * MF + hf * 128 + c8 * 8);
            float2 f0 = __half22float2(*(__half2*)&u.x);
            float2 f1 = __half22float2(*(__half2*)&u.y);
            float2 f2 = __half22float2(*(__half2*)&u.z);
            float2 f3 = __half22float2(*(__half2*)&u.w);
            float* dst = bufA + row * PA + c8 * 8;
            *(float4*)dst = make_float4(f0.x, f0.y, f1.x, f1.y);
            *(float4*)(dst + 4) = make_float4(f2.x, f2.y, f3.x, f3.y);
        }
        for (int it = 0; it < kkit; it++) {
            int idx = it * 256 + t;
            int row = idx >> 4, c8 = idx & 15;
            float ssel = (row < 64) ? sc0 : sc1;
            uint4 u = *(const uint4*)(kphb + (size_t)row * MF + hf * 128 + c8 * 8);
            float2 f0 = __half22float2(*(__half2*)&u.x);
            float2 f1 = __half22float2(*(__half2*)&u.y);
            float2 f2 = __half22float2(*(__half2*)&u.z);
            float2 f3 = __half22float2(*(__half2*)&u.w);
            __half2 h0 = __floats2half2_rn(fmaf(f0.x, ssel, ccst), fmaf(f0.y, ssel, ccst));
            __half2 h1 = __floats2half2_rn(fmaf(f1.x, ssel, ccst), fmaf(f1.y, ssel, ccst));
            __half2 h2 = __floats2half2_rn(fmaf(f2.x, ssel, ccst), fmaf(f2.y, ssel, ccst));
            __half2 h3 = __floats2half2_rn(fmaf(f3.x, ssel, ccst), fmaf(f3.y, ssel, ccst));
            uint4 o;
            o.x = *(uint32_t*)&h0; o.y = *(uint32_t*)&h1;
            o.z = *(uint32_t*)&h2; o.w = *(uint32_t*)&h3;
            *(uint4*)(bufKh + row * PKH + c8 * 8) = o;
        }
#pragma unroll
        for (int it = 0; it < 4; it++) {
            int idx = it * 256 + t;
            int row = idx >> 3, c8 = idx & 7;
            uint4 u = *(const uint4*)(Sbase + (size_t)(hf * 128 + row) * DHd + c8 * 8);
            float2 f0 = __half22float2(*(__half2*)&u.x);
            float2 f1 = __half22float2(*(__half2*)&u.y);
            float2 f2 = __half22float2(*(__half2*)&u.z);
            float2 f3 = __half22float2(*(__half2*)&u.w);
            float* dst = bufB1 + row * PB1 + c8 * 8;
            *(float4*)dst = make_float4(f0.x, f0.y, f1.x, f1.y);
            *(float4*)(dst + 4) = make_float4(f2.x, f2.y, f3.x, f3.y);
        }
        __syncthreads();
        if (hf == 0 && t < 64)
            den[t] = den4[4 * t] + den4[4 * t + 1] + den4[4 * t + 2] + den4[4 * t + 3];

#pragma unroll
        for (int ks = 0; ks < 8; ks++) {
            uint32_t af[2][4];
#pragma unroll
            for (int mt = 0; mt < 2; mt++) {
                const float* ap = bufA + (wm * 32 + mt * 16 + g) * PA + ks * 8 + tq;
                af[mt][0] = __float_as_uint(ap[0]);
                af[mt][1] = __float_as_uint(ap[8 * PA]);
                af[mt][2] = __float_as_uint(ap[4]);
                af[mt][3] = __float_as_uint(ap[8 * PA + 4]);
            }
#pragma unroll
            for (int nt = 0; nt < 4; nt++) {
                if (nt >= NT1) break;
                const __half* bp = bufKh + ((wn * NT1 + nt) * 8 + g) * PKH + ks * 8 + tq;
                uint32_t bf[2] = {__float_as_uint(__half2float(bp[0])),
                                  __float_as_uint(__half2float(bp[4]))};
                mma16n8k8(accA[0][nt], af[0], bf);
                mma16n8k8(accA[1][nt], af[1], bf);
            }
        }
#pragma unroll 2
        for (int ks = 0; ks < 16; ks++) {
            uint32_t af[2][4];
#pragma unroll
            for (int mt = 0; mt < 2; mt++) {
                const float* ap = bufA + (wm * 32 + mt * 16 + g) * PA + ks * 8 + tq;
                af[mt][0] = __float_as_uint(ap[0]);
                af[mt][1] = __float_as_uint(ap[8 * PA]);
                af[mt][2] = __float_as_uint(ap[4]);
                af[mt][3] = __float_as_uint(ap[8 * PA + 4]);
            }
#pragma unroll
            for (int nt = 0; nt < 2; nt++) {
                const float* bp = bufB1 + (ks * 8 + tq) * PB1 + (wn * 2 + nt) * 8 + g;
                uint32_t bf[2] = {__float_as_uint(bp[0]), __float_as_uint(bp[4 * PB1])};
                mma16n8k8(acc2[0][nt], af[0], bf);
                mma16n8k8(acc2[1][nt], af[1], bf);
            }
        }
#pragma unroll
        for (int ks = 0; ks < 8; ks++) {
            uint32_t af[2][4];
#pragma unroll
            for (int mt = 0; mt < 2; mt++) {
                const float* ap = bufA + (wm * 32 + mt * 16 + g) * PA + 64 + ks * 8 + tq;
                af[mt][0] = __float_as_uint(ap[0]);
                af[mt][1] = __float_as_uint(ap[8 * PA]);
                af[mt][2] = __float_as_uint(ap[4]);
                af[mt][3] = __float_as_uint(ap[8 * PA + 4]);
            }
#pragma unroll
            for (int nt = 0; nt < 4; nt++) {
                if (nt >= NT1) break;
                const __half* bp = bufKh + ((wn * NT1 + nt) * 8 + g) * PKH + 64 + ks * 8 + tq;
                uint32_t bf[2] = {__float_as_uint(__half2float(bp[0])),
                                  __float_as_uint(__half2float(bp[4]))};
                mma16n8k8(accA[0][nt], af[0], bf);
                mma16n8k8(accA[1][nt], af[1], bf);
            }
        }
    }

#pragma unroll
    for (int mt = 0; mt < 2; mt++) {
        int i0 = wm * 32 + mt * 16 + g;
        int lim0 = r0c + i0, lim1 = lim0 + 8;
        float rs0 = 0.f, rs1 = 0.f;
#pragma unroll
        for (int nt = 0; nt < 4; nt++) {
            if (nt >= NT1) break;
            int cb = (wn * NT1 + nt) * 8 + tq * 2;
            float v0 = (cb     <= lim0) ? accA[mt][nt][0] : 0.f;
            float v1 = (cb + 1 <= lim0) ? accA[mt][nt][1] : 0.f;
            float v2 = (cb     <= lim1) ? accA[mt][nt][2] : 0.f;
            float v3 = (cb + 1 <= lim1) ? accA[mt][nt][3] : 0.f;
            accA[mt][nt][0] = v0; accA[mt][nt][1] = v1;
            accA[mt][nt][2] = v2; accA[mt][nt][3] = v3;
            rs0 += v0 + v1;
            rs1 += v2 + v3;
        }
        rs0 += __shfl_xor_sync(0xffffffffu, rs0, 1);
        rs0 += __shfl_xor_sync(0xffffffffu, rs0, 2);
        rs1 += __shfl_xor_sync(0xffffffffu, rs1, 1);
        rs1 += __shfl_xor_sync(0xffffffffu, rs1, 2);
        if (tq == 0) {
            atomicAdd(&den[i0], rs0);
            atomicAdd(&den[i0 + 8], rs1);
        }
    }
    __syncthreads();

    if (t < 64) dinv[t] = 1.0f / den[t];
#pragma unroll
    for (int mt = 0; mt < 2; mt++) {
        int i0 = wm * 32 + mt * 16 + g;
#pragma unroll
        for (int nt = 0; nt < 4; nt++) {
            if (nt >= NT1) break;
            int j = (wn * NT1 + nt) * 8 + tq * 2;
            *(float2*)(bufA + i0 * PA + j) =
                make_float2(tf32r(accA[mt][nt][0]), tf32r(accA[mt][nt][1]));
            *(float2*)(bufA + (i0 + 8) * PA + j) =
                make_float2(tf32r(accA[mt][nt][2]), tf32r(accA[mt][nt][3]));
        }
    }
    for (int it = 0; it < kIters; it++) {
        int idx = it * 256 + t;
        int row = idx >> 4, c4 = idx & 15;
        float4 v = *(const float4*)(vin + ((size_t)(b * NN + n0 + row)) * Dd
                                    + h * DHd + c4 * 4);
        *(float4*)(bufB1 + row * PB1 + c4 * 4) = tf32v4(v);
    }
    __syncthreads();

#pragma unroll 2
    for (int ks = 0; ks < 16; ks++) {
        if (ks >= NJT) break;
        uint32_t af[2][4];
#pragma unroll
        for (int mt = 0; mt < 2; mt++) {
            const float* ap = bufA + (wm * 32 + mt * 16 + g) * PA + ks * 8 + tq;
            af[mt][0] = __float_as_uint(ap[0]);
            af[mt][1] = __float_as_uint(ap[8 * PA]);
            af[mt][2] = __float_as_uint(ap[4]);
            af[mt][3] = __float_as_uint(ap[8 * PA + 4]);
        }
#pragma unroll
        for (int nt = 0; nt < 2; nt++) {
            const float* bp = bufB1 + (ks * 8 + tq) * PB1 + (wn * 2 + nt) * 8 + g;
            uint32_t bf[2] = {__float_as_uint(bp[0]), __float_as_uint(bp[4 * PB1])};
            mma16n8k8(acc2[0][nt], af[0], bf);
            mma16n8k8(acc2[1][nt], af[1], bf);
        }
    }

#pragma unroll
    for (int mt = 0; mt < 2; mt++) {
        int i0 = wm * 32 + mt * 16 + g;
        float d0 = dinv[i0], d1 = dinv[i0 + 8];
        float* op0 = outp + ((size_t)(b * NN + n0 + r0c + i0)) * Dd + h * DHd;
        float* op1 = op0 + (size_t)8 * Dd;
#pragma unroll
        for (int nt = 0; nt < 2; nt++) {
            int e = (wn * 2 + nt) * 8 + tq * 2;
            *(float2*)(op0 + e) = make_float2(acc2[mt][nt][0] * d0,
                                              acc2[mt][nt][1] * d0);
            *(float2*)(op1 + e) = make_float2(acc2[mt][nt][2] * d1,
                                              acc2[mt][nt][3] * d1);
        }
    }
}

// ---------------------------------------------------------------------------
extern "C" void kernel_launch(void* const* d_in, const int* in_sizes, int n_in,
                              void* d_out, int out_size) {
    (void)in_sizes; (void)n_in; (void)out_size;
    const float* q    = (const float*)d_in[0];
    const float* k    = (const float*)d_in[1];
    const float* v    = (const float*)d_in[2];
    const float* proj = (const float*)d_in[3];
    float* out = (float*)d_out;

    cudaFuncSetAttribute(out_kernel, cudaFuncAttributeMaxDynamicSharedMemorySize,
                         OUT_DSMEM);

    feat_kernel<true><<<dim3(32, 32), 256>>>(q, proj);
    feat_kernel<false><<<dim3(32, 32), 256>>>(k, proj);
    chunk_kv_kernel<<<dim3(16, 32), 256>>>(v);
    prefix_kernel<<<1056, 256>>>();
    out_kernel<<<dim3(16, 32, 2), 256, OUT_DSMEM>>>(v, out);
}